// round 8
// baseline (speedup 1.0000x reference)
#include <cuda_runtime.h>

// Problem constants
#define BN_   10000
#define T_    8
#define C_    64
#define NM_   3
#define E_    160000
#define NTOT_ (T_ * BN_)        // 80000 node-rows
#define HTOT_ (NTOT_ * C_)      // 5,120,000

// Scratch (device globals: allocation-free rule)
__device__ __align__(16) float g_hnew[HTOT_];
__device__ __align__(16) float g_A[HTOT_];
__device__ __align__(16) float g_B[HTOT_];
__device__ __align__(16) float g_agg[HTOT_];
__device__ __align__(16) float g_d2[E_];

__constant__ float CT8[8] = {1.f,  0.70710678118654752f, 0.f, -0.70710678118654752f,
                             -1.f, -0.70710678118654752f, 0.f,  0.70710678118654752f};
__constant__ float ST8[8] = {0.f,  0.70710678118654752f, 1.f,  0.70710678118654752f,
                             0.f, -0.70710678118654752f, -1.f, -0.70710678118654752f};

typedef unsigned long long ull;

__device__ __forceinline__ float silu_f(float x)    { return x / (1.f + __expf(-x)); }
__device__ __forceinline__ float sigmoid_f(float x) { return 1.f / (1.f + __expf(-x)); }

__device__ __forceinline__ ull pk2(float lo, float hi) {
    ull r; asm("mov.b64 %0,{%1,%2};" : "=l"(r) : "f"(lo), "f"(hi)); return r;
}
__device__ __forceinline__ void upk2(ull v, float& lo, float& hi) {
    asm("mov.b64 {%0,%1},%2;" : "=f"(lo), "=f"(hi) : "l"(v));
}
__device__ __forceinline__ ull f2fma(ull a, ull b, ull c) {
    ull d; asm("fma.rn.f32x2 %0,%1,%2,%3;" : "=l"(d) : "l"(a), "l"(b), "l"(c)); return d;
}

// ---------------------------------------------------------------------------
// Kernel 1: TimeConv on h.  8 nodes/block, 2 nodes per phase-B thread.
// ---------------------------------------------------------------------------
__global__ void __launch_bounds__(256, 2) k_time_h(const float* __restrict__ h,
                                                   const float* __restrict__ whr,
                                                   const float* __restrict__ whi) {
    extern __shared__ float sm[];
    float* sWr12 = sm;            // [i*64+o]*2 : (wr1, wr2)
    float* sWi12 = sm + 8192;     // (wi1, wi2)
    float* sWr0  = sm + 16384;    // wr0
    float* sxf   = sm + 20480;    // [8 slot][64 i][8]
    const int tid = threadIdx.x;

    for (int idx = tid; idx < 4096; idx += 256) {
        int base = idx * 3;                  // (i*64+o)*3
        sWr12[idx * 2]     = whr[base + 1];
        sWr12[idx * 2 + 1] = whr[base + 2];
        sWi12[idx * 2]     = whi[base + 1];
        sWi12[idx * 2 + 1] = whi[base + 2];
        sWr0[idx]          = whr[base];
    }

    const int grp = tid >> 6;
    const int l   = tid & 63;
    const int node0 = blockIdx.x * 8 + grp * 2;

    // Phase A: rfft per (node, channel=l)
#pragma unroll
    for (int pp = 0; pp < 2; ++pp) {
        int node = node0 + pp;
        float xv[8];
#pragma unroll
        for (int t = 0; t < 8; ++t) xv[t] = h[t * (BN_ * C_) + node * C_ + l];
        float xr0 = 0.f, xr1 = 0.f, xi1 = 0.f, xr2 = 0.f, xi2 = 0.f;
#pragma unroll
        for (int t = 0; t < 8; ++t) {
            xr0 += xv[t];
            xr1 += xv[t] * CT8[t];
            xi1 -= xv[t] * ST8[t];
            xr2 += xv[t] * CT8[(2 * t) & 7];
            xi2 -= xv[t] * ST8[(2 * t) & 7];
        }
        float* p = sxf + (grp * 2 + pp) * 512 + l * 8;
        p[0] = xr1;  p[1] = xr2;
        p[2] = xi1;  p[3] = xi2;
        p[4] = -xi1; p[5] = -xi2;
        p[6] = xr0;  p[7] = 0.f;
    }
    __syncthreads();

    // Phase B: complex mix for o = l, 2 nodes (128-bit shared loads)
    ull omrA = pk2(0.f, 0.f), omiA = omrA, omrB = omrA, omiB = omrA;
    float om0A = 0.f, om0B = 0.f;
    const float* xA = sxf + grp * 1024;
    const float* xB = xA + 512;
#pragma unroll 4
    for (int i = 0; i < 64; ++i) {
        ull wr12 = *(const ull*)(sWr12 + (i * 64 + l) * 2);
        ull wi12 = *(const ull*)(sWi12 + (i * 64 + l) * 2);
        float wr0 = sWr0[i * 64 + l];
        const float* pa = xA + i * 8;
        const float* pb = xB + i * 8;
        ulonglong2 va = *(const ulonglong2*)pa;       // (xra, xia)
        ull nxa = *(const ull*)(pa + 4);
        ulonglong2 vb = *(const ulonglong2*)pb;
        ull nxb = *(const ull*)(pb + 4);
        omrA = f2fma(va.x, wr12, omrA); omrA = f2fma(nxa, wi12, omrA);
        omiA = f2fma(va.x, wi12, omiA); omiA = f2fma(va.y, wr12, omiA);
        om0A = fmaf(pa[6], wr0, om0A);
        omrB = f2fma(vb.x, wr12, omrB); omrB = f2fma(nxb, wi12, omrB);
        omiB = f2fma(vb.x, wi12, omiB); omiB = f2fma(vb.y, wr12, omiB);
        om0B = fmaf(pb[6], wr0, om0B);
    }

    // Phase C: irfft + leaky residual
#pragma unroll
    for (int pp = 0; pp < 2; ++pp) {
        int node = node0 + pp;
        float or1, or2, oi1, oi2, o0;
        if (pp == 0) { upk2(omrA, or1, or2); upk2(omiA, oi1, oi2); o0 = om0A; }
        else         { upk2(omrB, or1, or2); upk2(omiB, oi1, oi2); o0 = om0B; }
#pragma unroll
        for (int t = 0; t < 8; ++t) {
            float val = o0
                + 2.f * (or1 * CT8[t]           - oi1 * ST8[t])
                + 2.f * (or2 * CT8[(2 * t) & 7] - oi2 * ST8[(2 * t) & 7]);
            val *= 0.125f;
            float lr = val > 0.f ? val : 0.2f * val;
            int off = t * (BN_ * C_) + node * C_ + l;
            g_hnew[off] = h[off] + lr;
        }
    }
}

// ---------------------------------------------------------------------------
// Kernel 2: TimeConvX on velocity
// ---------------------------------------------------------------------------
__global__ void k_time_v(const float* __restrict__ vel,
                         const float* __restrict__ wvr,
                         const float* __restrict__ wvi,
                         float* __restrict__ out) {
    int j = blockIdx.x * blockDim.x + threadIdx.x;
    if (j >= BN_ * 3) return;
    int b = j / 3, d = j - b * 3;
    float xv[8];
#pragma unroll
    for (int t = 0; t < 8; ++t) xv[t] = vel[b * (T_ * 3) + t * 3 + d];
    float xr0 = 0.f, xr1 = 0.f, xi1 = 0.f, xr2 = 0.f, xi2 = 0.f;
#pragma unroll
    for (int t = 0; t < 8; ++t) {
        xr0 += xv[t];
        xr1 += xv[t] * CT8[t];
        xi1 -= xv[t] * ST8[t];
        xr2 += xv[t] * CT8[(2 * t) & 7];
        xi2 -= xv[t] * ST8[(2 * t) & 7];
    }
    float w0r = wvr[0];
    float w1r = wvr[1], w1i = wvi[1];
    float w2r = wvr[2], w2i = wvi[2];
    float yr0 = xr0 * w0r;
    float yr1 = xr1 * w1r - xi1 * w1i;
    float yi1 = xr1 * w1i + xi1 * w1r;
    float yr2 = xr2 * w2r - xi2 * w2i;
    float yi2 = xr2 * w2i + xi2 * w2r;
#pragma unroll
    for (int t = 0; t < 8; ++t) {
        float val = 0.125f * (yr0
            + 2.f * (yr1 * CT8[t]           - yi1 * ST8[t])
            + 2.f * (yr2 * CT8[(2 * t) & 7] - yi2 * ST8[(2 * t) & 7]));
        out[b * (T_ * 3) + t * 3 + d] = xv[t] + val;
    }
}

// ---------------------------------------------------------------------------
// Kernel 3: per-base-edge squared distance
// ---------------------------------------------------------------------------
__global__ void k_d2(const float* __restrict__ x, const int* __restrict__ ei) {
    int e = blockIdx.x * blockDim.x + threadIdx.x;
    if (e >= E_) return;
    int r = ei[e];
    int c = ei[E_ + e];
    float dx = x[r * 3 + 0] - x[c * 3 + 0];
    float dy = x[r * 3 + 1] - x[c * 3 + 1];
    float dz = x[r * 3 + 2] - x[c * 3 + 2];
    g_d2[e] = dx * dx + dy * dy + dz * dz;
}

// ---------------------------------------------------------------------------
// Kernel 4: A/B precompute as register-tiled GEMM.
// M=64 nodes/block, N=128 (A|B), K=64. 256 thr, thread tile 4m x 8n.
// ---------------------------------------------------------------------------
__global__ void __launch_bounds__(256, 4) k_ab(const float* __restrict__ We1,
                                               const float* __restrict__ be1) {
    extern __shared__ float sm[];
    float* sX = sm;              // [64][68]
    float* sW = sm + 4352;       // [64][132]
    float* sbias = sm + 12800;   // [128]
    const int tid = threadIdx.x;

    for (int idx = tid; idx < 8192; idx += 256) {
        int k = idx >> 7, n = idx & 127;
        float v = (n < 64) ? We1[k * 64 + n] : We1[(64 + k) * 64 + (n - 64)];
        sW[k * 132 + n] = v;
    }
    if (tid < 128) sbias[tid] = (tid < 64) ? be1[tid] : 0.f;

    const int nb = blockIdx.x * 64;
    {
        int row = tid >> 2, l4 = tid & 3;
        const float4* hp = (const float4*)(g_hnew + (size_t)(nb + row) * 64 + l4 * 16);
        float4* agp = (float4*)(g_agg + (size_t)(nb + row) * 64 + l4 * 16);
        float4* sx4 = (float4*)(sX + row * 68 + l4 * 16);
        float4 z = make_float4(0.f, 0.f, 0.f, 0.f);
#pragma unroll
        for (int jj = 0; jj < 4; ++jj) { sx4[jj] = hp[jj]; agp[jj] = z; }
    }
    __syncthreads();

    const int lane = tid & 31, w = tid >> 5;
    const int mw = w & 1, nw = w >> 1;         // nw 0..3
    const int mq = lane >> 2, nq = lane & 3;
    const int m0 = mw * 32 + mq;               // + i*8
    const int nbase = nw * 32 + nq * 4;        // + 16j

    ull acc[16];
#pragma unroll
    for (int i = 0; i < 4; ++i)
#pragma unroll
        for (int jj = 0; jj < 2; ++jj) {
            int n0 = nbase + 16 * jj;
            acc[i * 4 + jj * 2]     = pk2(sbias[n0],     sbias[n0 + 1]);
            acc[i * 4 + jj * 2 + 1] = pk2(sbias[n0 + 2], sbias[n0 + 3]);
        }

    const float* xp = sX + m0 * 68;
#pragma unroll 2
    for (int k4 = 0; k4 < 16; ++k4) {
        float xa[4][4];
#pragma unroll
        for (int i = 0; i < 4; ++i) {
            float4 v = *(const float4*)(xp + i * 8 * 68 + k4 * 4);
            xa[i][0] = v.x; xa[i][1] = v.y; xa[i][2] = v.z; xa[i][3] = v.w;
        }
#pragma unroll
        for (int kk = 0; kk < 4; ++kk) {
            const float* wrow = sW + (k4 * 4 + kk) * 132 + nbase;
            ulonglong2 wa = *(const ulonglong2*)(wrow);        // 1 LDS.128
            ulonglong2 wb = *(const ulonglong2*)(wrow + 16);   // 1 LDS.128
            ull wv[4] = {wa.x, wa.y, wb.x, wb.y};
#pragma unroll
            for (int i = 0; i < 4; ++i) {
                ull mk = pk2(xa[i][kk], xa[i][kk]);
#pragma unroll
                for (int jj = 0; jj < 4; ++jj)
                    acc[i * 4 + jj] = f2fma(mk, wv[jj], acc[i * 4 + jj]);
            }
        }
    }

#pragma unroll
    for (int i = 0; i < 4; ++i) {
        int node = nb + m0 + i * 8;
#pragma unroll
        for (int jj = 0; jj < 2; ++jj) {
            int n0 = nbase + 16 * jj;
            float4 v;
            upk2(acc[i * 4 + jj * 2],     v.x, v.y);
            upk2(acc[i * 4 + jj * 2 + 1], v.z, v.w);
            if (n0 < 64) *(float4*)(g_A + (size_t)node * 64 + n0) = v;
            else         *(float4*)(g_B + (size_t)node * 64 + (n0 - 64)) = v;
        }
    }
}

// ---------------------------------------------------------------------------
// Kernel 5: edge messages. 256 edges/block. 2 blocks/SM for phase overlap.
// ---------------------------------------------------------------------------
__global__ void __launch_bounds__(256, 2) k_edge(const int* __restrict__ ei,
                                                 const float* __restrict__ We1,
                                                 const float* __restrict__ We2,
                                                 const float* __restrict__ be2,
                                                 const float* __restrict__ Wg,
                                                 const float* __restrict__ bg) {
    extern __shared__ float sm[];
    float* sm1 = sm;                    // [256][68]
    float* sW2 = sm + 17408;            // [64][68]
    float* swl = sm + 21760;            // [64]
    float* sg  = sm + 21824;            // [64]
    float* sb2 = sm + 21888;            // [64]
    int*   srb = (int*)(sm + 21952);    // [256]
    const int tid = threadIdx.x;

    for (int idx = tid; idx < 4096; idx += 256)
        sW2[(idx >> 6) * 68 + (idx & 63)] = We2[idx];
    if (tid < 64) {
        swl[tid] = We1[128 * 64 + tid];
        sg[tid]  = Wg[tid];
        sb2[tid] = be2[tid];
    }
    __syncthreads();

    const int t  = blockIdx.x / 625;
    const int jb = (blockIdx.x - t * 625) * 256;

    // Phase 1
    {
        const int eIdx = tid >> 2, l4 = tid & 3;
#pragma unroll
        for (int p = 0; p < 4; ++p) {
            int e = p * 64 + eIdx;
            int j = jb + e;
            int rb = t * BN_ + __ldg(ei + j);
            int cb = t * BN_ + __ldg(ei + E_ + j);
            if (l4 == 0) srb[e] = rb;
            float dd = g_d2[j];
            const float4* Ap = (const float4*)(g_A + (size_t)rb * 64 + l4 * 16);
            const float4* Bp = (const float4*)(g_B + (size_t)cb * 64 + l4 * 16);
            const float4* wl = (const float4*)(swl + l4 * 16);
            float4* dst = (float4*)(sm1 + e * 68 + l4 * 16);
#pragma unroll
            for (int jj = 0; jj < 4; ++jj) {
                float4 a = Ap[jj], b = Bp[jj], ww = wl[jj];
                float4 o;
                o.x = silu_f(a.x + b.x + dd * ww.x);
                o.y = silu_f(a.y + b.y + dd * ww.y);
                o.z = silu_f(a.z + b.z + dd * ww.z);
                o.w = silu_f(a.w + b.w + dd * ww.w);
                dst[jj] = o;
            }
        }
    }
    __syncthreads();

    // Phase 2: GEMM  (warp w: edges w*32..w*32+31, all 64 outputs)
    const int lane = tid & 31, w = tid >> 5;
    const int mq = lane >> 2, nq = lane & 3;
    const int m0 = w * 32 + mq;                 // + i*8
    const int nbq = nq * 4;                     // + 16j

    ull acc[32];
#pragma unroll
    for (int i = 0; i < 4; ++i)
#pragma unroll
        for (int j = 0; j < 4; ++j) {
            int n0 = nbq + 16 * j;
            acc[i * 8 + j * 2]     = pk2(sb2[n0],     sb2[n0 + 1]);
            acc[i * 8 + j * 2 + 1] = pk2(sb2[n0 + 2], sb2[n0 + 3]);
        }

    const float* xp = sm1 + m0 * 68;
#pragma unroll 1
    for (int k4 = 0; k4 < 16; ++k4) {
        float xa[4][4];
#pragma unroll
        for (int i = 0; i < 4; ++i) {
            float4 v = *(const float4*)(xp + i * 8 * 68 + k4 * 4);
            xa[i][0] = v.x; xa[i][1] = v.y; xa[i][2] = v.z; xa[i][3] = v.w;
        }
#pragma unroll
        for (int kk = 0; kk < 4; ++kk) {
            const float* wrow = sW2 + (k4 * 4 + kk) * 68 + nbq;
            ull wv[8];
#pragma unroll
            for (int j = 0; j < 4; ++j) {
                ulonglong2 wj = *(const ulonglong2*)(wrow + 16 * j);  // 1 LDS.128
                wv[2 * j]     = wj.x;
                wv[2 * j + 1] = wj.y;
            }
#pragma unroll
            for (int i = 0; i < 4; ++i) {
                ull mk = pk2(xa[i][kk], xa[i][kk]);
#pragma unroll
                for (int jj = 0; jj < 8; ++jj)
                    acc[i * 8 + jj] = f2fma(mk, wv[jj], acc[i * 8 + jj]);
            }
        }
    }

    // Phase 3
    const float bgv = __ldg(bg);
#pragma unroll
    for (int i = 0; i < 4; ++i) {
        int m = m0 + i * 8;
        float v[16];
        float gp = 0.f;
#pragma unroll
        for (int j = 0; j < 4; ++j) {
            int n0 = nbq + 16 * j;
            float a, b, c, d;
            upk2(acc[i * 8 + j * 2],     a, b);
            upk2(acc[i * 8 + j * 2 + 1], c, d);
            a = silu_f(a); b = silu_f(b); c = silu_f(c); d = silu_f(d);
            v[j * 4] = a; v[j * 4 + 1] = b; v[j * 4 + 2] = c; v[j * 4 + 3] = d;
            gp += a * sg[n0] + b * sg[n0 + 1] + c * sg[n0 + 2] + d * sg[n0 + 3];
        }
        gp += __shfl_xor_sync(0xffffffffu, gp, 1);
        gp += __shfl_xor_sync(0xffffffffu, gp, 2);
        float gate = sigmoid_f(gp + bgv);
        float* ag = g_agg + (size_t)srb[m] * 64 + nbq;
#pragma unroll
        for (int j = 0; j < 4; ++j) {
            asm volatile("red.global.add.v4.f32 [%0], {%1,%2,%3,%4};" ::
                "l"(ag + 16 * j),
                "f"(gate * v[j * 4]),     "f"(gate * v[j * 4 + 1]),
                "f"(gate * v[j * 4 + 2]), "f"(gate * v[j * 4 + 3]) : "memory");
        }
    }
}

// ---------------------------------------------------------------------------
// Kernel 6: node update as two register-tiled GEMMs.
// ---------------------------------------------------------------------------
__global__ void __launch_bounds__(256, 2) k_node(const float* __restrict__ Wn1,
                                                 const float* __restrict__ bn1,
                                                 const float* __restrict__ Wn2,
                                                 const float* __restrict__ bn2,
                                                 float* __restrict__ out) {
    extern __shared__ float sm[];
    float* sX  = sm;            // [64][132] = [h | agg]
    float* sW1 = sm + 8448;     // [128][68]
    float* sU  = sm + 17152;    // [64][68]
    float* sW2 = sm + 21504;    // [64][68]
    float* sb1 = sm + 25856;    // [64]
    float* sb2 = sm + 25920;    // [64]
    const int tid = threadIdx.x;

    for (int idx = tid; idx < 8192; idx += 256)
        sW1[(idx >> 6) * 68 + (idx & 63)] = Wn1[idx];
    for (int idx = tid; idx < 4096; idx += 256)
        sW2[(idx >> 6) * 68 + (idx & 63)] = Wn2[idx];
    if (tid < 64) { sb1[tid] = bn1[tid]; sb2[tid] = bn2[tid]; }

    const int nb = blockIdx.x * 64;
    {
        int row = tid >> 2, l4 = tid & 3;
        const float4* hp = (const float4*)(g_hnew + (size_t)(nb + row) * 64 + l4 * 16);
        const float4* gp = (const float4*)(g_agg  + (size_t)(nb + row) * 64 + l4 * 16);
        float4* sxh = (float4*)(sX + row * 132 + l4 * 16);
        float4* sxa = (float4*)(sX + row * 132 + 64 + l4 * 16);
#pragma unroll
        for (int jj = 0; jj < 4; ++jj) { sxh[jj] = hp[jj]; sxa[jj] = gp[jj]; }
    }
    __syncthreads();

    const int lane = tid & 31, w = tid >> 5;
    const int mw = w & 3, nw = w >> 2;          // nw 0..1
    const int mq = lane >> 2, nq = lane & 3;
    const int m0 = mw * 16 + mq;                // + i*8, i 0..1
    const int nbase = nw * 32 + nq * 4;         // + 16j, j 0..1

    // ---- layer 1 (K = 128) ----
    ull acc[8];
#pragma unroll
    for (int i = 0; i < 2; ++i)
#pragma unroll
        for (int jj = 0; jj < 2; ++jj) {
            int n0 = nbase + 16 * jj;
            acc[i * 4 + jj * 2]     = pk2(sb1[n0],     sb1[n0 + 1]);
            acc[i * 4 + jj * 2 + 1] = pk2(sb1[n0 + 2], sb1[n0 + 3]);
        }
    const float* xp = sX + m0 * 132;
#pragma unroll 2
    for (int k4 = 0; k4 < 32; ++k4) {
        float xa[2][4];
#pragma unroll
        for (int i = 0; i < 2; ++i) {
            float4 v = *(const float4*)(xp + i * 8 * 132 + k4 * 4);
            xa[i][0] = v.x; xa[i][1] = v.y; xa[i][2] = v.z; xa[i][3] = v.w;
        }
#pragma unroll
        for (int kk = 0; kk < 4; ++kk) {
            const float* wrow = sW1 + (k4 * 4 + kk) * 68 + nbase;
            ulonglong2 wa = *(const ulonglong2*)(wrow);
            ulonglong2 wb = *(const ulonglong2*)(wrow + 16);
            ull wv[4] = {wa.x, wa.y, wb.x, wb.y};
#pragma unroll
            for (int i = 0; i < 2; ++i) {
                ull mk = pk2(xa[i][kk], xa[i][kk]);
#pragma unroll
                for (int jj = 0; jj < 4; ++jj)
                    acc[i * 4 + jj] = f2fma(mk, wv[jj], acc[i * 4 + jj]);
            }
        }
    }
#pragma unroll
    for (int i = 0; i < 2; ++i) {
        int m = m0 + i * 8;
#pragma unroll
        for (int jj = 0; jj < 2; ++jj) {
            int n0 = nbase + 16 * jj;
            float4 v;
            upk2(acc[i * 4 + jj * 2],     v.x, v.y);
            upk2(acc[i * 4 + jj * 2 + 1], v.z, v.w);
            v.x = silu_f(v.x); v.y = silu_f(v.y);
            v.z = silu_f(v.z); v.w = silu_f(v.w);
            *(float4*)(sU + m * 68 + n0) = v;
        }
    }
    __syncthreads();

    // ---- layer 2 (K = 64) ----
    ull acc2[8];
#pragma unroll
    for (int i = 0; i < 2; ++i)
#pragma unroll
        for (int jj = 0; jj < 2; ++jj) {
            int n0 = nbase + 16 * jj;
            acc2[i * 4 + jj * 2]     = pk2(sb2[n0],     sb2[n0 + 1]);
            acc2[i * 4 + jj * 2 + 1] = pk2(sb2[n0 + 2], sb2[n0 + 3]);
        }
    const float* up = sU + m0 * 68;
#pragma unroll 2
    for (int k4 = 0; k4 < 16; ++k4) {
        float xa[2][4];
#pragma unroll
        for (int i = 0; i < 2; ++i) {
            float4 v = *(const float4*)(up + i * 8 * 68 + k4 * 4);
            xa[i][0] = v.x; xa[i][1] = v.y; xa[i][2] = v.z; xa[i][3] = v.w;
        }
#pragma unroll
        for (int kk = 0; kk < 4; ++kk) {
            const float* wrow = sW2 + (k4 * 4 + kk) * 68 + nbase;
            ulonglong2 wa = *(const ulonglong2*)(wrow);
            ulonglong2 wb = *(const ulonglong2*)(wrow + 16);
            ull wv[4] = {wa.x, wa.y, wb.x, wb.y};
#pragma unroll
            for (int i = 0; i < 2; ++i) {
                ull mk = pk2(xa[i][kk], xa[i][kk]);
#pragma unroll
                for (int jj = 0; jj < 4; ++jj)
                    acc2[i * 4 + jj] = f2fma(mk, wv[jj], acc2[i * 4 + jj]);
            }
        }
    }
    // residual + store
#pragma unroll
    for (int i = 0; i < 2; ++i) {
        int m = m0 + i * 8;
        int node = nb + m;
#pragma unroll
        for (int jj = 0; jj < 2; ++jj) {
            int n0 = nbase + 16 * jj;
            float4 v;
            upk2(acc2[i * 4 + jj * 2],     v.x, v.y);
            upk2(acc2[i * 4 + jj * 2 + 1], v.z, v.w);
            float4 hv = *(const float4*)(sX + m * 132 + n0);
            v.x += hv.x; v.y += hv.y; v.z += hv.z; v.w += hv.w;
            *(float4*)(out + (size_t)node * 64 + n0) = v;
        }
    }
}

// ---------------------------------------------------------------------------
extern "C" void kernel_launch(void* const* d_in, const int* in_sizes, int n_in,
                              void* d_out, int out_size) {
    const float* h   = (const float*)d_in[0];
    const float* x   = (const float*)d_in[1];
    const float* vel = (const float*)d_in[2];
    const int*   ei  = (const int*)d_in[3];
    const float* whr = (const float*)d_in[4];
    const float* whi = (const float*)d_in[5];
    const float* wvr = (const float*)d_in[6];
    const float* wvi = (const float*)d_in[7];
    const float* We1 = (const float*)d_in[8];
    const float* be1 = (const float*)d_in[9];
    const float* We2 = (const float*)d_in[10];
    const float* be2 = (const float*)d_in[11];
    const float* Wg  = (const float*)d_in[12];
    const float* bg  = (const float*)d_in[13];
    const float* Wn1 = (const float*)d_in[14];
    const float* bn1 = (const float*)d_in[15];
    const float* Wn2 = (const float*)d_in[16];
    const float* bn2 = (const float*)d_in[17];
    float* out = (float*)d_out;

    (void)in_sizes; (void)n_in; (void)out_size;

    const int smem_h    = 24576 * 4;  // 98304
    const int smem_ab   = 12928 * 4;  // 51712
    const int smem_edge = 22208 * 4;  // 88832
    const int smem_node = 25984 * 4;  // 103936
    cudaFuncSetAttribute(k_time_h, cudaFuncAttributeMaxDynamicSharedMemorySize, smem_h);
    cudaFuncSetAttribute(k_ab,     cudaFuncAttributeMaxDynamicSharedMemorySize, smem_ab);
    cudaFuncSetAttribute(k_edge,   cudaFuncAttributeMaxDynamicSharedMemorySize, smem_edge);
    cudaFuncSetAttribute(k_node,   cudaFuncAttributeMaxDynamicSharedMemorySize, smem_node);

    // k_edge stays 4th so ncu captures it.
    k_d2<<<(E_ + 255) / 256, 256>>>(x, ei);
    k_time_h<<<1250, 256, smem_h>>>(h, whr, whi);
    k_ab<<<1250, 256, smem_ab>>>(We1, be1);
    k_edge<<<5000, 256, smem_edge>>>(ei, We1, We2, be2, Wg, bg);
    k_time_v<<<(BN_ * 3 + 255) / 256, 256>>>(vel, wvr, wvi, out + HTOT_);
    k_node<<<1250, 256, smem_node>>>(Wn1, bn1, Wn2, bn2, out);
}

// round 10
// speedup vs baseline: 1.0742x; 1.0742x over previous
#include <cuda_runtime.h>

// Problem constants
#define BN_   10000
#define T_    8
#define C_    64
#define NM_   3
#define E_    160000
#define NTOT_ (T_ * BN_)        // 80000 node-rows
#define HTOT_ (NTOT_ * C_)      // 5,120,000

// Scratch (device globals: allocation-free rule)
__device__ __align__(16) float g_hnew[HTOT_];
__device__ __align__(16) float g_A[HTOT_];
__device__ __align__(16) float g_B[HTOT_];
__device__ __align__(16) float g_agg[HTOT_];
__device__ __align__(16) float g_d2[E_];

__constant__ float CT8[8] = {1.f,  0.70710678118654752f, 0.f, -0.70710678118654752f,
                             -1.f, -0.70710678118654752f, 0.f,  0.70710678118654752f};
__constant__ float ST8[8] = {0.f,  0.70710678118654752f, 1.f,  0.70710678118654752f,
                             0.f, -0.70710678118654752f, -1.f, -0.70710678118654752f};

typedef unsigned long long ull;

__device__ __forceinline__ float silu_f(float x)    { return x / (1.f + __expf(-x)); }
__device__ __forceinline__ float sigmoid_f(float x) { return 1.f / (1.f + __expf(-x)); }

__device__ __forceinline__ ull pk2(float lo, float hi) {
    ull r; asm("mov.b64 %0,{%1,%2};" : "=l"(r) : "f"(lo), "f"(hi)); return r;
}
__device__ __forceinline__ void upk2(ull v, float& lo, float& hi) {
    asm("mov.b64 {%0,%1},%2;" : "=f"(lo), "=f"(hi) : "l"(v));
}
__device__ __forceinline__ ull f2fma(ull a, ull b, ull c) {
    ull d; asm("fma.rn.f32x2 %0,%1,%2,%3;" : "=l"(d) : "l"(a), "l"(b), "l"(c)); return d;
}

// ---------------------------------------------------------------------------
// Kernel 1: TimeConv on h.  8 nodes/block, 2 nodes per phase-B thread.
// ---------------------------------------------------------------------------
__global__ void __launch_bounds__(256, 2) k_time_h(const float* __restrict__ h,
                                                   const float* __restrict__ whr,
                                                   const float* __restrict__ whi) {
    extern __shared__ float sm[];
    float* sWr12 = sm;            // [i*64+o]*2 : (wr1, wr2)
    float* sWi12 = sm + 8192;     // (wi1, wi2)
    float* sWr0  = sm + 16384;    // wr0
    float* sxf   = sm + 20480;    // [8 slot][64 i][8]
    const int tid = threadIdx.x;

    for (int idx = tid; idx < 4096; idx += 256) {
        int base = idx * 3;                  // (i*64+o)*3
        sWr12[idx * 2]     = whr[base + 1];
        sWr12[idx * 2 + 1] = whr[base + 2];
        sWi12[idx * 2]     = whi[base + 1];
        sWi12[idx * 2 + 1] = whi[base + 2];
        sWr0[idx]          = whr[base];
    }

    const int grp = tid >> 6;
    const int l   = tid & 63;
    const int node0 = blockIdx.x * 8 + grp * 2;

    // Phase A: rfft per (node, channel=l)
#pragma unroll
    for (int pp = 0; pp < 2; ++pp) {
        int node = node0 + pp;
        float xv[8];
#pragma unroll
        for (int t = 0; t < 8; ++t) xv[t] = h[t * (BN_ * C_) + node * C_ + l];
        float xr0 = 0.f, xr1 = 0.f, xi1 = 0.f, xr2 = 0.f, xi2 = 0.f;
#pragma unroll
        for (int t = 0; t < 8; ++t) {
            xr0 += xv[t];
            xr1 += xv[t] * CT8[t];
            xi1 -= xv[t] * ST8[t];
            xr2 += xv[t] * CT8[(2 * t) & 7];
            xi2 -= xv[t] * ST8[(2 * t) & 7];
        }
        float* p = sxf + (grp * 2 + pp) * 512 + l * 8;
        p[0] = xr1;  p[1] = xr2;
        p[2] = xi1;  p[3] = xi2;
        p[4] = -xi1; p[5] = -xi2;
        p[6] = xr0;  p[7] = 0.f;
    }
    __syncthreads();

    // Phase B: complex mix for o = l, 2 nodes (128-bit shared loads)
    ull omrA = pk2(0.f, 0.f), omiA = omrA, omrB = omrA, omiB = omrA;
    float om0A = 0.f, om0B = 0.f;
    const float* xA = sxf + grp * 1024;
    const float* xB = xA + 512;
#pragma unroll 4
    for (int i = 0; i < 64; ++i) {
        ull wr12 = *(const ull*)(sWr12 + (i * 64 + l) * 2);
        ull wi12 = *(const ull*)(sWi12 + (i * 64 + l) * 2);
        float wr0 = sWr0[i * 64 + l];
        const float* pa = xA + i * 8;
        const float* pb = xB + i * 8;
        ulonglong2 va = *(const ulonglong2*)pa;       // (xra, xia)
        ull nxa = *(const ull*)(pa + 4);
        ulonglong2 vb = *(const ulonglong2*)pb;
        ull nxb = *(const ull*)(pb + 4);
        omrA = f2fma(va.x, wr12, omrA); omrA = f2fma(nxa, wi12, omrA);
        omiA = f2fma(va.x, wi12, omiA); omiA = f2fma(va.y, wr12, omiA);
        om0A = fmaf(pa[6], wr0, om0A);
        omrB = f2fma(vb.x, wr12, omrB); omrB = f2fma(nxb, wi12, omrB);
        omiB = f2fma(vb.x, wi12, omiB); omiB = f2fma(vb.y, wr12, omiB);
        om0B = fmaf(pb[6], wr0, om0B);
    }

    // Phase C: irfft + leaky residual
#pragma unroll
    for (int pp = 0; pp < 2; ++pp) {
        int node = node0 + pp;
        float or1, or2, oi1, oi2, o0;
        if (pp == 0) { upk2(omrA, or1, or2); upk2(omiA, oi1, oi2); o0 = om0A; }
        else         { upk2(omrB, or1, or2); upk2(omiB, oi1, oi2); o0 = om0B; }
#pragma unroll
        for (int t = 0; t < 8; ++t) {
            float val = o0
                + 2.f * (or1 * CT8[t]           - oi1 * ST8[t])
                + 2.f * (or2 * CT8[(2 * t) & 7] - oi2 * ST8[(2 * t) & 7]);
            val *= 0.125f;
            float lr = val > 0.f ? val : 0.2f * val;
            int off = t * (BN_ * C_) + node * C_ + l;
            g_hnew[off] = h[off] + lr;
        }
    }
}

// ---------------------------------------------------------------------------
// Kernel 2: TimeConvX on velocity
// ---------------------------------------------------------------------------
__global__ void k_time_v(const float* __restrict__ vel,
                         const float* __restrict__ wvr,
                         const float* __restrict__ wvi,
                         float* __restrict__ out) {
    int j = blockIdx.x * blockDim.x + threadIdx.x;
    if (j >= BN_ * 3) return;
    int b = j / 3, d = j - b * 3;
    float xv[8];
#pragma unroll
    for (int t = 0; t < 8; ++t) xv[t] = vel[b * (T_ * 3) + t * 3 + d];
    float xr0 = 0.f, xr1 = 0.f, xi1 = 0.f, xr2 = 0.f, xi2 = 0.f;
#pragma unroll
    for (int t = 0; t < 8; ++t) {
        xr0 += xv[t];
        xr1 += xv[t] * CT8[t];
        xi1 -= xv[t] * ST8[t];
        xr2 += xv[t] * CT8[(2 * t) & 7];
        xi2 -= xv[t] * ST8[(2 * t) & 7];
    }
    float w0r = wvr[0];
    float w1r = wvr[1], w1i = wvi[1];
    float w2r = wvr[2], w2i = wvi[2];
    float yr0 = xr0 * w0r;
    float yr1 = xr1 * w1r - xi1 * w1i;
    float yi1 = xr1 * w1i + xi1 * w1r;
    float yr2 = xr2 * w2r - xi2 * w2i;
    float yi2 = xr2 * w2i + xi2 * w2r;
#pragma unroll
    for (int t = 0; t < 8; ++t) {
        float val = 0.125f * (yr0
            + 2.f * (yr1 * CT8[t]           - yi1 * ST8[t])
            + 2.f * (yr2 * CT8[(2 * t) & 7] - yi2 * ST8[(2 * t) & 7]));
        out[b * (T_ * 3) + t * 3 + d] = xv[t] + val;
    }
}

// ---------------------------------------------------------------------------
// Kernel 3: per-base-edge squared distance
// ---------------------------------------------------------------------------
__global__ void k_d2(const float* __restrict__ x, const int* __restrict__ ei) {
    int e = blockIdx.x * blockDim.x + threadIdx.x;
    if (e >= E_) return;
    int r = ei[e];
    int c = ei[E_ + e];
    float dx = x[r * 3 + 0] - x[c * 3 + 0];
    float dy = x[r * 3 + 1] - x[c * 3 + 1];
    float dz = x[r * 3 + 2] - x[c * 3 + 2];
    g_d2[e] = dx * dx + dy * dy + dz * dz;
}

// ---------------------------------------------------------------------------
// Kernel 4: A/B precompute as register-tiled GEMM.
// M=64 nodes/block, N=128 (A|B), K=64. 256 thr, thread tile 4m x 8n.
// ---------------------------------------------------------------------------
__global__ void __launch_bounds__(256, 4) k_ab(const float* __restrict__ We1,
                                               const float* __restrict__ be1) {
    extern __shared__ float sm[];
    float* sX = sm;              // [64][68]
    float* sW = sm + 4352;       // [64][132]
    float* sbias = sm + 12800;   // [128]
    const int tid = threadIdx.x;

    for (int idx = tid; idx < 8192; idx += 256) {
        int k = idx >> 7, n = idx & 127;
        float v = (n < 64) ? We1[k * 64 + n] : We1[(64 + k) * 64 + (n - 64)];
        sW[k * 132 + n] = v;
    }
    if (tid < 128) sbias[tid] = (tid < 64) ? be1[tid] : 0.f;

    const int nb = blockIdx.x * 64;
    {
        int row = tid >> 2, l4 = tid & 3;
        const float4* hp = (const float4*)(g_hnew + (size_t)(nb + row) * 64 + l4 * 16);
        float4* agp = (float4*)(g_agg + (size_t)(nb + row) * 64 + l4 * 16);
        float4* sx4 = (float4*)(sX + row * 68 + l4 * 16);
        float4 z = make_float4(0.f, 0.f, 0.f, 0.f);
#pragma unroll
        for (int jj = 0; jj < 4; ++jj) { sx4[jj] = hp[jj]; agp[jj] = z; }
    }
    __syncthreads();

    const int lane = tid & 31, w = tid >> 5;
    const int mw = w & 1, nw = w >> 1;         // nw 0..3
    const int mq = lane >> 2, nq = lane & 3;
    const int m0 = mw * 32 + mq;               // + i*8
    const int nbase = nw * 32 + nq * 4;        // + 16j

    ull acc[16];
#pragma unroll
    for (int i = 0; i < 4; ++i)
#pragma unroll
        for (int jj = 0; jj < 2; ++jj) {
            int n0 = nbase + 16 * jj;
            acc[i * 4 + jj * 2]     = pk2(sbias[n0],     sbias[n0 + 1]);
            acc[i * 4 + jj * 2 + 1] = pk2(sbias[n0 + 2], sbias[n0 + 3]);
        }

    const float* xp = sX + m0 * 68;
#pragma unroll 2
    for (int k4 = 0; k4 < 16; ++k4) {
        float xa[4][4];
#pragma unroll
        for (int i = 0; i < 4; ++i) {
            float4 v = *(const float4*)(xp + i * 8 * 68 + k4 * 4);
            xa[i][0] = v.x; xa[i][1] = v.y; xa[i][2] = v.z; xa[i][3] = v.w;
        }
#pragma unroll
        for (int kk = 0; kk < 4; ++kk) {
            const float* wrow = sW + (k4 * 4 + kk) * 132 + nbase;
            ulonglong2 wa = *(const ulonglong2*)(wrow);        // 1 LDS.128
            ulonglong2 wb = *(const ulonglong2*)(wrow + 16);   // 1 LDS.128
            ull wv[4] = {wa.x, wa.y, wb.x, wb.y};
#pragma unroll
            for (int i = 0; i < 4; ++i) {
                ull mk = pk2(xa[i][kk], xa[i][kk]);
#pragma unroll
                for (int jj = 0; jj < 4; ++jj)
                    acc[i * 4 + jj] = f2fma(mk, wv[jj], acc[i * 4 + jj]);
            }
        }
    }

#pragma unroll
    for (int i = 0; i < 4; ++i) {
        int node = nb + m0 + i * 8;
#pragma unroll
        for (int jj = 0; jj < 2; ++jj) {
            int n0 = nbase + 16 * jj;
            float4 v;
            upk2(acc[i * 4 + jj * 2],     v.x, v.y);
            upk2(acc[i * 4 + jj * 2 + 1], v.z, v.w);
            if (n0 < 64) *(float4*)(g_A + (size_t)node * 64 + n0) = v;
            else         *(float4*)(g_B + (size_t)node * 64 + (n0 - 64)) = v;
        }
    }
}

// ---------------------------------------------------------------------------
// Kernel 5: edge messages. 128 edges/block, 3 blocks/SM.
// Warp pair (g, nhalf): warp handles 32 edges x 32 outputs (thread 4m x 8n,
// acc = 16 ull = 32 regs). Gate dot spans the two halves -> smem partials.
// ---------------------------------------------------------------------------
__global__ void __launch_bounds__(256, 3) k_edge(const int* __restrict__ ei,
                                                 const float* __restrict__ We1,
                                                 const float* __restrict__ We2,
                                                 const float* __restrict__ be2,
                                                 const float* __restrict__ Wg,
                                                 const float* __restrict__ bg) {
    extern __shared__ float sm[];
    float* sm1 = sm;                    // [128][68]
    float* sW2 = sm + 8704;             // [64][68]
    float* swl = sm + 13056;            // [64]
    float* sg  = sm + 13120;            // [64]
    float* sb2 = sm + 13184;            // [64]
    int*   srb = (int*)(sm + 13248);    // [128]
    float* sgp = sm + 13376;            // [2][128] gate partials
    const int tid = threadIdx.x;

    for (int idx = tid; idx < 4096; idx += 256)
        sW2[(idx >> 6) * 68 + (idx & 63)] = We2[idx];
    if (tid < 64) {
        swl[tid] = We1[128 * 64 + tid];
        sg[tid]  = Wg[tid];
        sb2[tid] = be2[tid];
    }
    __syncthreads();

    const int t  = blockIdx.x / 1250;
    const int jb = (blockIdx.x - t * 1250) * 128;

    // Phase 1: m1 = silu(A[rb] + B[cb] + d2*wl) for 128 edges
    {
        const int eIdx = tid >> 2, l4 = tid & 3;
#pragma unroll
        for (int p = 0; p < 2; ++p) {
            int e = p * 64 + eIdx;
            int j = jb + e;
            int rb = t * BN_ + __ldg(ei + j);
            int cb = t * BN_ + __ldg(ei + E_ + j);
            if (l4 == 0) srb[e] = rb;
            float dd = g_d2[j];
            const float4* Ap = (const float4*)(g_A + (size_t)rb * 64 + l4 * 16);
            const float4* Bp = (const float4*)(g_B + (size_t)cb * 64 + l4 * 16);
            const float4* wl = (const float4*)(swl + l4 * 16);
            float4* dst = (float4*)(sm1 + e * 68 + l4 * 16);
#pragma unroll
            for (int jj = 0; jj < 4; ++jj) {
                float4 a = Ap[jj], b = Bp[jj], ww = wl[jj];
                float4 o;
                o.x = silu_f(a.x + b.x + dd * ww.x);
                o.y = silu_f(a.y + b.y + dd * ww.y);
                o.z = silu_f(a.z + b.z + dd * ww.z);
                o.w = silu_f(a.w + b.w + dd * ww.w);
                dst[jj] = o;
            }
        }
    }
    __syncthreads();

    // Phase 2: GEMM. warp w = (g, nh): edges g*32..+31, outputs nh*32..+31.
    const int lane = tid & 31, w = tid >> 5;
    const int g  = w >> 1, nh = w & 1;
    const int mq = lane >> 2, nq = lane & 3;
    const int m0 = g * 32 + mq;                 // + i*8
    const int nb0 = nh * 32 + nq * 4;           // + 16j

    ull acc[16];
#pragma unroll
    for (int i = 0; i < 4; ++i)
#pragma unroll
        for (int j = 0; j < 2; ++j) {
            int n0 = nb0 + 16 * j;
            acc[i * 4 + j * 2]     = pk2(sb2[n0],     sb2[n0 + 1]);
            acc[i * 4 + j * 2 + 1] = pk2(sb2[n0 + 2], sb2[n0 + 3]);
        }

    const float* xp = sm1 + m0 * 68;
#pragma unroll 2
    for (int k4 = 0; k4 < 16; ++k4) {
        float xa[4][4];
#pragma unroll
        for (int i = 0; i < 4; ++i) {
            float4 v = *(const float4*)(xp + i * 8 * 68 + k4 * 4);
            xa[i][0] = v.x; xa[i][1] = v.y; xa[i][2] = v.z; xa[i][3] = v.w;
        }
#pragma unroll
        for (int kk = 0; kk < 4; ++kk) {
            const float* wrow = sW2 + (k4 * 4 + kk) * 68 + nb0;
            ulonglong2 wa = *(const ulonglong2*)(wrow);
            ulonglong2 wb = *(const ulonglong2*)(wrow + 16);
            ull wv[4] = {wa.x, wa.y, wb.x, wb.y};
#pragma unroll
            for (int i = 0; i < 4; ++i) {
                ull mk = pk2(xa[i][kk], xa[i][kk]);
#pragma unroll
                for (int jj = 0; jj < 4; ++jj)
                    acc[i * 4 + jj] = f2fma(mk, wv[jj], acc[i * 4 + jj]);
            }
        }
    }

    // Phase 3a: silu in place, partial gate dot (over this warp's 32 n)
#pragma unroll
    for (int i = 0; i < 4; ++i) {
        float d = 0.f;
#pragma unroll
        for (int jj = 0; jj < 4; ++jj) {
            int n0 = nb0 + (jj >> 1) * 16 + (jj & 1) * 2;
            float a, b;
            upk2(acc[i * 4 + jj], a, b);
            a = silu_f(a); b = silu_f(b);
            d += a * sg[n0] + b * sg[n0 + 1];
            acc[i * 4 + jj] = pk2(a, b);
        }
        d += __shfl_xor_sync(0xffffffffu, d, 1);
        d += __shfl_xor_sync(0xffffffffu, d, 2);
        if (nq == 0) sgp[nh * 128 + m0 + i * 8] = d;
    }
    __syncthreads();

    // Phase 3b: full gate, vectorized REDs for this warp's n-half
    const float bgv = __ldg(bg);
#pragma unroll
    for (int i = 0; i < 4; ++i) {
        int m = m0 + i * 8;
        float gate = sigmoid_f(sgp[m] + sgp[128 + m] + bgv);
        float* ag = g_agg + (size_t)srb[m] * 64 + nb0;
#pragma unroll
        for (int j = 0; j < 2; ++j) {
            float a, b, c, d;
            upk2(acc[i * 4 + j * 2],     a, b);
            upk2(acc[i * 4 + j * 2 + 1], c, d);
            asm volatile("red.global.add.v4.f32 [%0], {%1,%2,%3,%4};" ::
                "l"(ag + 16 * j),
                "f"(gate * a), "f"(gate * b), "f"(gate * c), "f"(gate * d)
                : "memory");
        }
    }
}

// ---------------------------------------------------------------------------
// Kernel 6: node update as two register-tiled GEMMs.
// ---------------------------------------------------------------------------
__global__ void __launch_bounds__(256, 2) k_node(const float* __restrict__ Wn1,
                                                 const float* __restrict__ bn1,
                                                 const float* __restrict__ Wn2,
                                                 const float* __restrict__ bn2,
                                                 float* __restrict__ out) {
    extern __shared__ float sm[];
    float* sX  = sm;            // [64][132] = [h | agg]
    float* sW1 = sm + 8448;     // [128][68]
    float* sU  = sm + 17152;    // [64][68]
    float* sW2 = sm + 21504;    // [64][68]
    float* sb1 = sm + 25856;    // [64]
    float* sb2 = sm + 25920;    // [64]
    const int tid = threadIdx.x;

    for (int idx = tid; idx < 8192; idx += 256)
        sW1[(idx >> 6) * 68 + (idx & 63)] = Wn1[idx];
    for (int idx = tid; idx < 4096; idx += 256)
        sW2[(idx >> 6) * 68 + (idx & 63)] = Wn2[idx];
    if (tid < 64) { sb1[tid] = bn1[tid]; sb2[tid] = bn2[tid]; }

    const int nb = blockIdx.x * 64;
    {
        int row = tid >> 2, l4 = tid & 3;
        const float4* hp = (const float4*)(g_hnew + (size_t)(nb + row) * 64 + l4 * 16);
        const float4* gp = (const float4*)(g_agg  + (size_t)(nb + row) * 64 + l4 * 16);
        float4* sxh = (float4*)(sX + row * 132 + l4 * 16);
        float4* sxa = (float4*)(sX + row * 132 + 64 + l4 * 16);
#pragma unroll
        for (int jj = 0; jj < 4; ++jj) { sxh[jj] = hp[jj]; sxa[jj] = gp[jj]; }
    }
    __syncthreads();

    const int lane = tid & 31, w = tid >> 5;
    const int mw = w & 3, nw = w >> 2;          // nw 0..1
    const int mq = lane >> 2, nq = lane & 3;
    const int m0 = mw * 16 + mq;                // + i*8, i 0..1
    const int nbase = nw * 32 + nq * 4;         // + 16j, j 0..1

    // ---- layer 1 (K = 128) ----
    ull acc[8];
#pragma unroll
    for (int i = 0; i < 2; ++i)
#pragma unroll
        for (int jj = 0; jj < 2; ++jj) {
            int n0 = nbase + 16 * jj;
            acc[i * 4 + jj * 2]     = pk2(sb1[n0],     sb1[n0 + 1]);
            acc[i * 4 + jj * 2 + 1] = pk2(sb1[n0 + 2], sb1[n0 + 3]);
        }
    const float* xp = sX + m0 * 132;
#pragma unroll 2
    for (int k4 = 0; k4 < 32; ++k4) {
        float xa[2][4];
#pragma unroll
        for (int i = 0; i < 2; ++i) {
            float4 v = *(const float4*)(xp + i * 8 * 132 + k4 * 4);
            xa[i][0] = v.x; xa[i][1] = v.y; xa[i][2] = v.z; xa[i][3] = v.w;
        }
#pragma unroll
        for (int kk = 0; kk < 4; ++kk) {
            const float* wrow = sW1 + (k4 * 4 + kk) * 68 + nbase;
            ulonglong2 wa = *(const ulonglong2*)(wrow);
            ulonglong2 wb = *(const ulonglong2*)(wrow + 16);
            ull wv[4] = {wa.x, wa.y, wb.x, wb.y};
#pragma unroll
            for (int i = 0; i < 2; ++i) {
                ull mk = pk2(xa[i][kk], xa[i][kk]);
#pragma unroll
                for (int jj = 0; jj < 4; ++jj)
                    acc[i * 4 + jj] = f2fma(mk, wv[jj], acc[i * 4 + jj]);
            }
        }
    }
#pragma unroll
    for (int i = 0; i < 2; ++i) {
        int m = m0 + i * 8;
#pragma unroll
        for (int jj = 0; jj < 2; ++jj) {
            int n0 = nbase + 16 * jj;
            float4 v;
            upk2(acc[i * 4 + jj * 2],     v.x, v.y);
            upk2(acc[i * 4 + jj * 2 + 1], v.z, v.w);
            v.x = silu_f(v.x); v.y = silu_f(v.y);
            v.z = silu_f(v.z); v.w = silu_f(v.w);
            *(float4*)(sU + m * 68 + n0) = v;
        }
    }
    __syncthreads();

    // ---- layer 2 (K = 64) ----
    ull acc2[8];
#pragma unroll
    for (int i = 0; i < 2; ++i)
#pragma unroll
        for (int jj = 0; jj < 2; ++jj) {
            int n0 = nbase + 16 * jj;
            acc2[i * 4 + jj * 2]     = pk2(sb2[n0],     sb2[n0 + 1]);
            acc2[i * 4 + jj * 2 + 1] = pk2(sb2[n0 + 2], sb2[n0 + 3]);
        }
    const float* up = sU + m0 * 68;
#pragma unroll 2
    for (int k4 = 0; k4 < 16; ++k4) {
        float xa[2][4];
#pragma unroll
        for (int i = 0; i < 2; ++i) {
            float4 v = *(const float4*)(up + i * 8 * 68 + k4 * 4);
            xa[i][0] = v.x; xa[i][1] = v.y; xa[i][2] = v.z; xa[i][3] = v.w;
        }
#pragma unroll
        for (int kk = 0; kk < 4; ++kk) {
            const float* wrow = sW2 + (k4 * 4 + kk) * 68 + nbase;
            ulonglong2 wa = *(const ulonglong2*)(wrow);
            ulonglong2 wb = *(const ulonglong2*)(wrow + 16);
            ull wv[4] = {wa.x, wa.y, wb.x, wb.y};
#pragma unroll
            for (int i = 0; i < 2; ++i) {
                ull mk = pk2(xa[i][kk], xa[i][kk]);
#pragma unroll
                for (int jj = 0; jj < 4; ++jj)
                    acc2[i * 4 + jj] = f2fma(mk, wv[jj], acc2[i * 4 + jj]);
            }
        }
    }
    // residual + store
#pragma unroll
    for (int i = 0; i < 2; ++i) {
        int m = m0 + i * 8;
        int node = nb + m;
#pragma unroll
        for (int jj = 0; jj < 2; ++jj) {
            int n0 = nbase + 16 * jj;
            float4 v;
            upk2(acc2[i * 4 + jj * 2],     v.x, v.y);
            upk2(acc2[i * 4 + jj * 2 + 1], v.z, v.w);
            float4 hv = *(const float4*)(sX + m * 132 + n0);
            v.x += hv.x; v.y += hv.y; v.z += hv.z; v.w += hv.w;
            *(float4*)(out + (size_t)node * 64 + n0) = v;
        }
    }
}

// ---------------------------------------------------------------------------
extern "C" void kernel_launch(void* const* d_in, const int* in_sizes, int n_in,
                              void* d_out, int out_size) {
    const float* h   = (const float*)d_in[0];
    const float* x   = (const float*)d_in[1];
    const float* vel = (const float*)d_in[2];
    const int*   ei  = (const int*)d_in[3];
    const float* whr = (const float*)d_in[4];
    const float* whi = (const float*)d_in[5];
    const float* wvr = (const float*)d_in[6];
    const float* wvi = (const float*)d_in[7];
    const float* We1 = (const float*)d_in[8];
    const float* be1 = (const float*)d_in[9];
    const float* We2 = (const float*)d_in[10];
    const float* be2 = (const float*)d_in[11];
    const float* Wg  = (const float*)d_in[12];
    const float* bg  = (const float*)d_in[13];
    const float* Wn1 = (const float*)d_in[14];
    const float* bn1 = (const float*)d_in[15];
    const float* Wn2 = (const float*)d_in[16];
    const float* bn2 = (const float*)d_in[17];
    float* out = (float*)d_out;

    (void)in_sizes; (void)n_in; (void)out_size;

    const int smem_h    = 24576 * 4;  // 98304
    const int smem_ab   = 12928 * 4;  // 51712
    const int smem_edge = 13632 * 4;  // 54528
    const int smem_node = 25984 * 4;  // 103936
    cudaFuncSetAttribute(k_time_h, cudaFuncAttributeMaxDynamicSharedMemorySize, smem_h);
    cudaFuncSetAttribute(k_ab,     cudaFuncAttributeMaxDynamicSharedMemorySize, smem_ab);
    cudaFuncSetAttribute(k_edge,   cudaFuncAttributeMaxDynamicSharedMemorySize, smem_edge);
    cudaFuncSetAttribute(k_node,   cudaFuncAttributeMaxDynamicSharedMemorySize, smem_node);

    // k_edge stays 4th so ncu captures it.
    k_d2<<<(E_ + 255) / 256, 256>>>(x, ei);
    k_time_h<<<1250, 256, smem_h>>>(h, whr, whi);
    k_ab<<<1250, 256, smem_ab>>>(We1, be1);
    k_edge<<<10000, 256, smem_edge>>>(ei, We1, We2, be2, Wg, bg);
    k_time_v<<<(BN_ * 3 + 255) / 256, 256>>>(vel, wvr, wvi, out + HTOT_);
    k_node<<<1250, 256, smem_node>>>(Wn1, bn1, Wn2, bn2, out);
}

// round 13
// speedup vs baseline: 1.1798x; 1.0983x over previous
#include <cuda_runtime.h>

// Problem constants
#define BN_   10000
#define T_    8
#define C_    64
#define NM_   3
#define E_    160000
#define NTOT_ (T_ * BN_)        // 80000 node-rows
#define HTOT_ (NTOT_ * C_)      // 5,120,000

// Scratch (device globals: allocation-free rule)
__device__ __align__(16) float g_hnew[HTOT_];
__device__ __align__(16) float g_A[HTOT_];
__device__ __align__(16) float g_B[HTOT_];
__device__ __align__(16) float g_agg[HTOT_];
__device__ __align__(16) float g_d2[E_];

__constant__ float CT8[8] = {1.f,  0.70710678118654752f, 0.f, -0.70710678118654752f,
                             -1.f, -0.70710678118654752f, 0.f,  0.70710678118654752f};
__constant__ float ST8[8] = {0.f,  0.70710678118654752f, 1.f,  0.70710678118654752f,
                             0.f, -0.70710678118654752f, -1.f, -0.70710678118654752f};

typedef unsigned long long ull;

__device__ __forceinline__ float silu_f(float x)    { return x / (1.f + __expf(-x)); }
__device__ __forceinline__ float sigmoid_f(float x) { return 1.f / (1.f + __expf(-x)); }

__device__ __forceinline__ ull pk2(float lo, float hi) {
    ull r; asm("mov.b64 %0,{%1,%2};" : "=l"(r) : "f"(lo), "f"(hi)); return r;
}
__device__ __forceinline__ void upk2(ull v, float& lo, float& hi) {
    asm("mov.b64 {%0,%1},%2;" : "=f"(lo), "=f"(hi) : "l"(v));
}
__device__ __forceinline__ ull f2fma(ull a, ull b, ull c) {
    ull d; asm("fma.rn.f32x2 %0,%1,%2,%3;" : "=l"(d) : "l"(a), "l"(b), "l"(c)); return d;
}
// tf32 destination is a b32 register per PTX ISA -> "=r" constraint.
__device__ __forceinline__ float tf32r(float x) {
    unsigned int y; asm("cvt.rna.tf32.f32 %0,%1;" : "=r"(y) : "f"(x));
    return __uint_as_float(y);
}

#define MMA_TF32(c, a, b) \
    asm volatile("mma.sync.aligned.m16n8k8.row.col.f32.tf32.tf32.f32 " \
        "{%0,%1,%2,%3}, {%4,%5,%6,%7}, {%8,%9}, {%0,%1,%2,%3};" \
        : "+f"((c)[0]), "+f"((c)[1]), "+f"((c)[2]), "+f"((c)[3]) \
        : "r"(__float_as_uint((a)[0])), "r"(__float_as_uint((a)[1])), \
          "r"(__float_as_uint((a)[2])), "r"(__float_as_uint((a)[3])), \
          "r"(__float_as_uint((b)[0])), "r"(__float_as_uint((b)[1])))

// ---------------------------------------------------------------------------
// Kernel 1: TimeConv on h.  8 nodes/block, 2 nodes per phase-B thread.
// ---------------------------------------------------------------------------
__global__ void __launch_bounds__(256, 2) k_time_h(const float* __restrict__ h,
                                                   const float* __restrict__ whr,
                                                   const float* __restrict__ whi) {
    extern __shared__ float sm[];
    float* sWr12 = sm;            // [i*64+o]*2 : (wr1, wr2)
    float* sWi12 = sm + 8192;     // (wi1, wi2)
    float* sWr0  = sm + 16384;    // wr0
    float* sxf   = sm + 20480;    // [8 slot][64 i][8]
    const int tid = threadIdx.x;

    for (int idx = tid; idx < 4096; idx += 256) {
        int base = idx * 3;                  // (i*64+o)*3
        sWr12[idx * 2]     = whr[base + 1];
        sWr12[idx * 2 + 1] = whr[base + 2];
        sWi12[idx * 2]     = whi[base + 1];
        sWi12[idx * 2 + 1] = whi[base + 2];
        sWr0[idx]          = whr[base];
    }

    const int grp = tid >> 6;
    const int l   = tid & 63;
    const int node0 = blockIdx.x * 8 + grp * 2;

    // Phase A: rfft per (node, channel=l)
#pragma unroll
    for (int pp = 0; pp < 2; ++pp) {
        int node = node0 + pp;
        float xv[8];
#pragma unroll
        for (int t = 0; t < 8; ++t) xv[t] = h[t * (BN_ * C_) + node * C_ + l];
        float xr0 = 0.f, xr1 = 0.f, xi1 = 0.f, xr2 = 0.f, xi2 = 0.f;
#pragma unroll
        for (int t = 0; t < 8; ++t) {
            xr0 += xv[t];
            xr1 += xv[t] * CT8[t];
            xi1 -= xv[t] * ST8[t];
            xr2 += xv[t] * CT8[(2 * t) & 7];
            xi2 -= xv[t] * ST8[(2 * t) & 7];
        }
        float* p = sxf + (grp * 2 + pp) * 512 + l * 8;
        p[0] = xr1;  p[1] = xr2;
        p[2] = xi1;  p[3] = xi2;
        p[4] = -xi1; p[5] = -xi2;
        p[6] = xr0;  p[7] = 0.f;
    }
    __syncthreads();

    // Phase B: complex mix for o = l, 2 nodes (128-bit shared loads)
    ull omrA = pk2(0.f, 0.f), omiA = omrA, omrB = omrA, omiB = omrA;
    float om0A = 0.f, om0B = 0.f;
    const float* xA = sxf + grp * 1024;
    const float* xB = xA + 512;
#pragma unroll 4
    for (int i = 0; i < 64; ++i) {
        ull wr12 = *(const ull*)(sWr12 + (i * 64 + l) * 2);
        ull wi12 = *(const ull*)(sWi12 + (i * 64 + l) * 2);
        float wr0 = sWr0[i * 64 + l];
        const float* pa = xA + i * 8;
        const float* pb = xB + i * 8;
        ulonglong2 va = *(const ulonglong2*)pa;       // (xra, xia)
        ull nxa = *(const ull*)(pa + 4);
        ulonglong2 vb = *(const ulonglong2*)pb;
        ull nxb = *(const ull*)(pb + 4);
        omrA = f2fma(va.x, wr12, omrA); omrA = f2fma(nxa, wi12, omrA);
        omiA = f2fma(va.x, wi12, omiA); omiA = f2fma(va.y, wr12, omiA);
        om0A = fmaf(pa[6], wr0, om0A);
        omrB = f2fma(vb.x, wr12, omrB); omrB = f2fma(nxb, wi12, omrB);
        omiB = f2fma(vb.x, wi12, omiB); omiB = f2fma(vb.y, wr12, omiB);
        om0B = fmaf(pb[6], wr0, om0B);
    }

    // Phase C: irfft + leaky residual
#pragma unroll
    for (int pp = 0; pp < 2; ++pp) {
        int node = node0 + pp;
        float or1, or2, oi1, oi2, o0;
        if (pp == 0) { upk2(omrA, or1, or2); upk2(omiA, oi1, oi2); o0 = om0A; }
        else         { upk2(omrB, or1, or2); upk2(omiB, oi1, oi2); o0 = om0B; }
#pragma unroll
        for (int t = 0; t < 8; ++t) {
            float val = o0
                + 2.f * (or1 * CT8[t]           - oi1 * ST8[t])
                + 2.f * (or2 * CT8[(2 * t) & 7] - oi2 * ST8[(2 * t) & 7]);
            val *= 0.125f;
            float lr = val > 0.f ? val : 0.2f * val;
            int off = t * (BN_ * C_) + node * C_ + l;
            g_hnew[off] = h[off] + lr;
        }
    }
}

// ---------------------------------------------------------------------------
// Kernel 2: TimeConvX on velocity
// ---------------------------------------------------------------------------
__global__ void k_time_v(const float* __restrict__ vel,
                         const float* __restrict__ wvr,
                         const float* __restrict__ wvi,
                         float* __restrict__ out) {
    int j = blockIdx.x * blockDim.x + threadIdx.x;
    if (j >= BN_ * 3) return;
    int b = j / 3, d = j - b * 3;
    float xv[8];
#pragma unroll
    for (int t = 0; t < 8; ++t) xv[t] = vel[b * (T_ * 3) + t * 3 + d];
    float xr0 = 0.f, xr1 = 0.f, xi1 = 0.f, xr2 = 0.f, xi2 = 0.f;
#pragma unroll
    for (int t = 0; t < 8; ++t) {
        xr0 += xv[t];
        xr1 += xv[t] * CT8[t];
        xi1 -= xv[t] * ST8[t];
        xr2 += xv[t] * CT8[(2 * t) & 7];
        xi2 -= xv[t] * ST8[(2 * t) & 7];
    }
    float w0r = wvr[0];
    float w1r = wvr[1], w1i = wvi[1];
    float w2r = wvr[2], w2i = wvi[2];
    float yr0 = xr0 * w0r;
    float yr1 = xr1 * w1r - xi1 * w1i;
    float yi1 = xr1 * w1i + xi1 * w1r;
    float yr2 = xr2 * w2r - xi2 * w2i;
    float yi2 = xr2 * w2i + xi2 * w2r;
#pragma unroll
    for (int t = 0; t < 8; ++t) {
        float val = 0.125f * (yr0
            + 2.f * (yr1 * CT8[t]           - yi1 * ST8[t])
            + 2.f * (yr2 * CT8[(2 * t) & 7] - yi2 * ST8[(2 * t) & 7]));
        out[b * (T_ * 3) + t * 3 + d] = xv[t] + val;
    }
}

// ---------------------------------------------------------------------------
// Kernel 3: per-base-edge squared distance
// ---------------------------------------------------------------------------
__global__ void k_d2(const float* __restrict__ x, const int* __restrict__ ei) {
    int e = blockIdx.x * blockDim.x + threadIdx.x;
    if (e >= E_) return;
    int r = ei[e];
    int c = ei[E_ + e];
    float dx = x[r * 3 + 0] - x[c * 3 + 0];
    float dy = x[r * 3 + 1] - x[c * 3 + 1];
    float dz = x[r * 3 + 2] - x[c * 3 + 2];
    g_d2[e] = dx * dx + dy * dy + dz * dz;
}

// ---------------------------------------------------------------------------
// Kernel 4: A/B precompute as register-tiled GEMM.
// M=64 nodes/block, N=128 (A|B), K=64. 256 thr, thread tile 4m x 8n.
// ---------------------------------------------------------------------------
__global__ void __launch_bounds__(256, 4) k_ab(const float* __restrict__ We1,
                                               const float* __restrict__ be1) {
    extern __shared__ float sm[];
    float* sX = sm;              // [64][68]
    float* sW = sm + 4352;       // [64][132]
    float* sbias = sm + 12800;   // [128]
    const int tid = threadIdx.x;

    for (int idx = tid; idx < 8192; idx += 256) {
        int k = idx >> 7, n = idx & 127;
        float v = (n < 64) ? We1[k * 64 + n] : We1[(64 + k) * 64 + (n - 64)];
        sW[k * 132 + n] = v;
    }
    if (tid < 128) sbias[tid] = (tid < 64) ? be1[tid] : 0.f;

    const int nb = blockIdx.x * 64;
    {
        int row = tid >> 2, l4 = tid & 3;
        const float4* hp = (const float4*)(g_hnew + (size_t)(nb + row) * 64 + l4 * 16);
        float4* agp = (float4*)(g_agg + (size_t)(nb + row) * 64 + l4 * 16);
        float4* sx4 = (float4*)(sX + row * 68 + l4 * 16);
        float4 z = make_float4(0.f, 0.f, 0.f, 0.f);
#pragma unroll
        for (int jj = 0; jj < 4; ++jj) { sx4[jj] = hp[jj]; agp[jj] = z; }
    }
    __syncthreads();

    const int lane = tid & 31, w = tid >> 5;
    const int mw = w & 1, nw = w >> 1;         // nw 0..3
    const int mq = lane >> 2, nq = lane & 3;
    const int m0 = mw * 32 + mq;               // + i*8
    const int nbase = nw * 32 + nq * 4;        // + 16j

    ull acc[16];
#pragma unroll
    for (int i = 0; i < 4; ++i)
#pragma unroll
        for (int jj = 0; jj < 2; ++jj) {
            int n0 = nbase + 16 * jj;
            acc[i * 4 + jj * 2]     = pk2(sbias[n0],     sbias[n0 + 1]);
            acc[i * 4 + jj * 2 + 1] = pk2(sbias[n0 + 2], sbias[n0 + 3]);
        }

    const float* xp = sX + m0 * 68;
#pragma unroll 2
    for (int k4 = 0; k4 < 16; ++k4) {
        float xa[4][4];
#pragma unroll
        for (int i = 0; i < 4; ++i) {
            float4 v = *(const float4*)(xp + i * 8 * 68 + k4 * 4);
            xa[i][0] = v.x; xa[i][1] = v.y; xa[i][2] = v.z; xa[i][3] = v.w;
        }
#pragma unroll
        for (int kk = 0; kk < 4; ++kk) {
            const float* wrow = sW + (k4 * 4 + kk) * 132 + nbase;
            ulonglong2 wa = *(const ulonglong2*)(wrow);        // 1 LDS.128
            ulonglong2 wb = *(const ulonglong2*)(wrow + 16);   // 1 LDS.128
            ull wv[4] = {wa.x, wa.y, wb.x, wb.y};
#pragma unroll
            for (int i = 0; i < 4; ++i) {
                ull mk = pk2(xa[i][kk], xa[i][kk]);
#pragma unroll
                for (int jj = 0; jj < 4; ++jj)
                    acc[i * 4 + jj] = f2fma(mk, wv[jj], acc[i * 4 + jj]);
            }
        }
    }

#pragma unroll
    for (int i = 0; i < 4; ++i) {
        int node = nb + m0 + i * 8;
#pragma unroll
        for (int jj = 0; jj < 2; ++jj) {
            int n0 = nbase + 16 * jj;
            float4 v;
            upk2(acc[i * 4 + jj * 2],     v.x, v.y);
            upk2(acc[i * 4 + jj * 2 + 1], v.z, v.w);
            if (n0 < 64) *(float4*)(g_A + (size_t)node * 64 + n0) = v;
            else         *(float4*)(g_B + (size_t)node * 64 + (n0 - 64)) = v;
        }
    }
}

// ---------------------------------------------------------------------------
// Kernel 5: edge messages. 128 edges/block, 3 blocks/SM.
// Phase 2 is tf32 mma.sync (m16n8k8): warp (g2, nh) computes
// 32 edges x 32 outputs via 2x4x8 mma tiles. Both operands tf32-rounded
// at staging time (cvt.rna). Fragment scalar LDS are conflict-free.
// ---------------------------------------------------------------------------
__global__ void __launch_bounds__(256, 3) k_edge(const int* __restrict__ ei,
                                                 const float* __restrict__ We1,
                                                 const float* __restrict__ We2,
                                                 const float* __restrict__ be2,
                                                 const float* __restrict__ Wg,
                                                 const float* __restrict__ bg) {
    extern __shared__ float sm[];
    float* sm1  = sm;                   // [128][68]  m1, tf32-rounded
    float* sW2t = sm + 8704;            // [64][68]  We2 transposed [n][k], tf32-rounded
    float* swl  = sm + 13056;           // [64]
    float* sg   = sm + 13120;           // [64]
    float* sb2  = sm + 13184;           // [64]
    int*   srb  = (int*)(sm + 13248);   // [128]
    float* sgp  = sm + 13376;           // [2][128] gate partials
    const int tid = threadIdx.x;

    for (int idx = tid; idx < 4096; idx += 256) {
        int k = idx >> 6, n = idx & 63;
        sW2t[n * 68 + k] = tf32r(We2[k * 64 + n]);
    }
    if (tid < 64) {
        swl[tid] = We1[128 * 64 + tid];
        sg[tid]  = Wg[tid];
        sb2[tid] = be2[tid];
    }
    __syncthreads();

    const int t  = blockIdx.x / 1250;
    const int jb = (blockIdx.x - t * 1250) * 128;

    // Phase 1: m1 = tf32(silu(A[rb] + B[cb] + d2*wl)) for 128 edges
    {
        const int eIdx = tid >> 2, l4 = tid & 3;
#pragma unroll
        for (int p = 0; p < 2; ++p) {
            int e = p * 64 + eIdx;
            int j = jb + e;
            int rb = t * BN_ + __ldg(ei + j);
            int cb = t * BN_ + __ldg(ei + E_ + j);
            if (l4 == 0) srb[e] = rb;
            float dd = g_d2[j];
            const float4* Ap = (const float4*)(g_A + (size_t)rb * 64 + l4 * 16);
            const float4* Bp = (const float4*)(g_B + (size_t)cb * 64 + l4 * 16);
            const float4* wl = (const float4*)(swl + l4 * 16);
            float4* dst = (float4*)(sm1 + e * 68 + l4 * 16);
#pragma unroll
            for (int jj = 0; jj < 4; ++jj) {
                float4 a = Ap[jj], b = Bp[jj], ww = wl[jj];
                float4 o;
                o.x = tf32r(silu_f(a.x + b.x + dd * ww.x));
                o.y = tf32r(silu_f(a.y + b.y + dd * ww.y));
                o.z = tf32r(silu_f(a.z + b.z + dd * ww.z));
                o.w = tf32r(silu_f(a.w + b.w + dd * ww.w));
                dst[jj] = o;
            }
        }
    }
    __syncthreads();

    // Phase 2: tf32 mma. warp w = (g2, nh): edges g2*32..+31, outputs nh*32..+31.
    const int lane = tid & 31, w = tid >> 5;
    const int g2 = w >> 1, nh = w & 1;
    const int gId = lane >> 2, tig = lane & 3;
    const int m0w = g2 * 32;
    const int nhb = nh * 32;

    float acc[2][4][4];
#pragma unroll
    for (int mi = 0; mi < 2; ++mi)
#pragma unroll
        for (int nj = 0; nj < 4; ++nj) {
            float b0v = sb2[nhb + nj * 8 + 2 * tig];
            float b1v = sb2[nhb + nj * 8 + 2 * tig + 1];
            acc[mi][nj][0] = b0v; acc[mi][nj][1] = b1v;
            acc[mi][nj][2] = b0v; acc[mi][nj][3] = b1v;
        }

#pragma unroll
    for (int ki = 0; ki < 8; ++ki) {
        const int kb = ki * 8 + tig;
        float a[2][4], b[4][2];
#pragma unroll
        for (int mi = 0; mi < 2; ++mi) {
            const float* r0 = sm1 + (m0w + mi * 16 + gId) * 68;
            a[mi][0] = r0[kb];
            a[mi][1] = r0[8 * 68 + kb];
            a[mi][2] = r0[kb + 4];
            a[mi][3] = r0[8 * 68 + kb + 4];
        }
#pragma unroll
        for (int nj = 0; nj < 4; ++nj) {
            const float* bn = sW2t + (nhb + nj * 8 + gId) * 68;
            b[nj][0] = bn[kb];
            b[nj][1] = bn[kb + 4];
        }
#pragma unroll
        for (int mi = 0; mi < 2; ++mi)
#pragma unroll
            for (int nj = 0; nj < 4; ++nj)
                MMA_TF32(acc[mi][nj], a[mi], b[nj]);
    }

    // Phase 3a: silu in place + partial gate dot (this warp's 32 n)
#pragma unroll
    for (int mi = 0; mi < 2; ++mi)
#pragma unroll
        for (int half = 0; half < 2; ++half) {
            int lm = m0w + mi * 16 + gId + half * 8;
            float d = 0.f;
#pragma unroll
            for (int nj = 0; nj < 4; ++nj) {
                int n0 = nhb + nj * 8 + 2 * tig;
                float s0 = silu_f(acc[mi][nj][half * 2]);
                float s1 = silu_f(acc[mi][nj][half * 2 + 1]);
                acc[mi][nj][half * 2]     = s0;
                acc[mi][nj][half * 2 + 1] = s1;
                d += s0 * sg[n0] + s1 * sg[n0 + 1];
            }
            d += __shfl_xor_sync(0xffffffffu, d, 1);
            d += __shfl_xor_sync(0xffffffffu, d, 2);
            if (tig == 0) sgp[nh * 128 + lm] = d;
        }
    __syncthreads();

    // Phase 3b: full gate, v2 REDs for this warp's n-half
    const float bgv = __ldg(bg);
#pragma unroll
    for (int mi = 0; mi < 2; ++mi)
#pragma unroll
        for (int half = 0; half < 2; ++half) {
            int lm = m0w + mi * 16 + gId + half * 8;
            float gate = sigmoid_f(sgp[lm] + sgp[128 + lm] + bgv);
            float* ag = g_agg + (size_t)srb[lm] * 64;
#pragma unroll
            for (int nj = 0; nj < 4; ++nj) {
                int n0 = nhb + nj * 8 + 2 * tig;
                asm volatile("red.global.add.v2.f32 [%0], {%1,%2};" ::
                    "l"(ag + n0),
                    "f"(gate * acc[mi][nj][half * 2]),
                    "f"(gate * acc[mi][nj][half * 2 + 1]) : "memory");
            }
        }
}

// ---------------------------------------------------------------------------
// Kernel 6: node update as two register-tiled GEMMs.
// ---------------------------------------------------------------------------
__global__ void __launch_bounds__(256, 2) k_node(const float* __restrict__ Wn1,
                                                 const float* __restrict__ bn1,
                                                 const float* __restrict__ Wn2,
                                                 const float* __restrict__ bn2,
                                                 float* __restrict__ out) {
    extern __shared__ float sm[];
    float* sX  = sm;            // [64][132] = [h | agg]
    float* sW1 = sm + 8448;     // [128][68]
    float* sU  = sm + 17152;    // [64][68]
    float* sW2 = sm + 21504;    // [64][68]
    float* sb1 = sm + 25856;    // [64]
    float* sb2 = sm + 25920;    // [64]
    const int tid = threadIdx.x;

    for (int idx = tid; idx < 8192; idx += 256)
        sW1[(idx >> 6) * 68 + (idx & 63)] = Wn1[idx];
    for (int idx = tid; idx < 4096; idx += 256)
        sW2[(idx >> 6) * 68 + (idx & 63)] = Wn2[idx];
    if (tid < 64) { sb1[tid] = bn1[tid]; sb2[tid] = bn2[tid]; }

    const int nb = blockIdx.x * 64;
    {
        int row = tid >> 2, l4 = tid & 3;
        const float4* hp = (const float4*)(g_hnew + (size_t)(nb + row) * 64 + l4 * 16);
        const float4* gp = (const float4*)(g_agg  + (size_t)(nb + row) * 64 + l4 * 16);
        float4* sxh = (float4*)(sX + row * 132 + l4 * 16);
        float4* sxa = (float4*)(sX + row * 132 + 64 + l4 * 16);
#pragma unroll
        for (int jj = 0; jj < 4; ++jj) { sxh[jj] = hp[jj]; sxa[jj] = gp[jj]; }
    }
    __syncthreads();

    const int lane = tid & 31, w = tid >> 5;
    const int mw = w & 3, nw = w >> 2;          // nw 0..1
    const int mq = lane >> 2, nq = lane & 3;
    const int m0 = mw * 16 + mq;                // + i*8, i 0..1
    const int nbase = nw * 32 + nq * 4;         // + 16j, j 0..1

    // ---- layer 1 (K = 128) ----
    ull acc[8];
#pragma unroll
    for (int i = 0; i < 2; ++i)
#pragma unroll
        for (int jj = 0; jj < 2; ++jj) {
            int n0 = nbase + 16 * jj;
            acc[i * 4 + jj * 2]     = pk2(sb1[n0],     sb1[n0 + 1]);
            acc[i * 4 + jj * 2 + 1] = pk2(sb1[n0 + 2], sb1[n0 + 3]);
        }
    const float* xp = sX + m0 * 132;
#pragma unroll 2
    for (int k4 = 0; k4 < 32; ++k4) {
        float xa[2][4];
#pragma unroll
        for (int i = 0; i < 2; ++i) {
            float4 v = *(const float4*)(xp + i * 8 * 132 + k4 * 4);
            xa[i][0] = v.x; xa[i][1] = v.y; xa[i][2] = v.z; xa[i][3] = v.w;
        }
#pragma unroll
        for (int kk = 0; kk < 4; ++kk) {
            const float* wrow = sW1 + (k4 * 4 + kk) * 68 + nbase;
            ulonglong2 wa = *(const ulonglong2*)(wrow);
            ulonglong2 wb = *(const ulonglong2*)(wrow + 16);
            ull wv[4] = {wa.x, wa.y, wb.x, wb.y};
#pragma unroll
            for (int i = 0; i < 2; ++i) {
                ull mk = pk2(xa[i][kk], xa[i][kk]);
#pragma unroll
                for (int jj = 0; jj < 4; ++jj)
                    acc[i * 4 + jj] = f2fma(mk, wv[jj], acc[i * 4 + jj]);
            }
        }
    }
#pragma unroll
    for (int i = 0; i < 2; ++i) {
        int m = m0 + i * 8;
#pragma unroll
        for (int jj = 0; jj < 2; ++jj) {
            int n0 = nbase + 16 * jj;
            float4 v;
            upk2(acc[i * 4 + jj * 2],     v.x, v.y);
            upk2(acc[i * 4 + jj * 2 + 1], v.z, v.w);
            v.x = silu_f(v.x); v.y = silu_f(v.y);
            v.z = silu_f(v.z); v.w = silu_f(v.w);
            *(float4*)(sU + m * 68 + n0) = v;
        }
    }
    __syncthreads();

    // ---- layer 2 (K = 64) ----
    ull acc2[8];
#pragma unroll
    for (int i = 0; i < 2; ++i)
#pragma unroll
        for (int jj = 0; jj < 2; ++jj) {
            int n0 = nbase + 16 * jj;
            acc2[i * 4 + jj * 2]     = pk2(sb2[n0],     sb2[n0 + 1]);
            acc2[i * 4 + jj * 2 + 1] = pk2(sb2[n0 + 2], sb2[n0 + 3]);
        }
    const float* up = sU + m0 * 68;
#pragma unroll 2
    for (int k4 = 0; k4 < 16; ++k4) {
        float xa[2][4];
#pragma unroll
        for (int i = 0; i < 2; ++i) {
            float4 v = *(const float4*)(up + i * 8 * 68 + k4 * 4);
            xa[i][0] = v.x; xa[i][1] = v.y; xa[i][2] = v.z; xa[i][3] = v.w;
        }
#pragma unroll
        for (int kk = 0; kk < 4; ++kk) {
            const float* wrow = sW2 + (k4 * 4 + kk) * 68 + nbase;
            ulonglong2 wa = *(const ulonglong2*)(wrow);
            ulonglong2 wb = *(const ulonglong2*)(wrow + 16);
            ull wv[4] = {wa.x, wa.y, wb.x, wb.y};
#pragma unroll
            for (int i = 0; i < 2; ++i) {
                ull mk = pk2(xa[i][kk], xa[i][kk]);
#pragma unroll
                for (int jj = 0; jj < 4; ++jj)
                    acc2[i * 4 + jj] = f2fma(mk, wv[jj], acc2[i * 4 + jj]);
            }
        }
    }
    // residual + store
#pragma unroll
    for (int i = 0; i < 2; ++i) {
        int m = m0 + i * 8;
        int node = nb + m;
#pragma unroll
        for (int jj = 0; jj < 2; ++jj) {
            int n0 = nbase + 16 * jj;
            float4 v;
            upk2(acc2[i * 4 + jj * 2],     v.x, v.y);
            upk2(acc2[i * 4 + jj * 2 + 1], v.z, v.w);
            float4 hv = *(const float4*)(sX + m * 132 + n0);
            v.x += hv.x; v.y += hv.y; v.z += hv.z; v.w += hv.w;
            *(float4*)(out + (size_t)node * 64 + n0) = v;
        }
    }
}

// ---------------------------------------------------------------------------
extern "C" void kernel_launch(void* const* d_in, const int* in_sizes, int n_in,
                              void* d_out, int out_size) {
    const float* h   = (const float*)d_in[0];
    const float* x   = (const float*)d_in[1];
    const float* vel = (const float*)d_in[2];
    const int*   ei  = (const int*)d_in[3];
    const float* whr = (const float*)d_in[4];
    const float* whi = (const float*)d_in[5];
    const float* wvr = (const float*)d_in[6];
    const float* wvi = (const float*)d_in[7];
    const float* We1 = (const float*)d_in[8];
    const float* be1 = (const float*)d_in[9];
    const float* We2 = (const float*)d_in[10];
    const float* be2 = (const float*)d_in[11];
    const float* Wg  = (const float*)d_in[12];
    const float* bg  = (const float*)d_in[13];
    const float* Wn1 = (const float*)d_in[14];
    const float* bn1 = (const float*)d_in[15];
    const float* Wn2 = (const float*)d_in[16];
    const float* bn2 = (const float*)d_in[17];
    float* out = (float*)d_out;

    (void)in_sizes; (void)n_in; (void)out_size;

    const int smem_h    = 24576 * 4;  // 98304
    const int smem_ab   = 12928 * 4;  // 51712
    const int smem_edge = 13632 * 4;  // 54528
    const int smem_node = 25984 * 4;  // 103936
    cudaFuncSetAttribute(k_time_h, cudaFuncAttributeMaxDynamicSharedMemorySize, smem_h);
    cudaFuncSetAttribute(k_ab,     cudaFuncAttributeMaxDynamicSharedMemorySize, smem_ab);
    cudaFuncSetAttribute(k_edge,   cudaFuncAttributeMaxDynamicSharedMemorySize, smem_edge);
    cudaFuncSetAttribute(k_node,   cudaFuncAttributeMaxDynamicSharedMemorySize, smem_node);

    // k_edge stays 4th so ncu captures it.
    k_d2<<<(E_ + 255) / 256, 256>>>(x, ei);
    k_time_h<<<1250, 256, smem_h>>>(h, whr, whi);
    k_ab<<<1250, 256, smem_ab>>>(We1, be1);
    k_edge<<<10000, 256, smem_edge>>>(ei, We1, We2, be2, Wg, bg);
    k_time_v<<<(BN_ * 3 + 255) / 256, 256>>>(vel, wvr, wvi, out + HTOT_);
    k_node<<<1250, 256, smem_node>>>(Wn1, bn1, Wn2, bn2, out);
}

// round 15
// speedup vs baseline: 1.2271x; 1.0401x over previous
#include <cuda_runtime.h>

// Problem constants
#define BN_   10000
#define T_    8
#define C_    64
#define NM_   3
#define E_    160000
#define NTOT_ (T_ * BN_)        // 80000 node-rows
#define HTOT_ (NTOT_ * C_)      // 5,120,000

// Scratch (device globals: allocation-free rule)
__device__ __align__(16) float g_hnew[HTOT_];
__device__ __align__(16) float g_A[HTOT_];
__device__ __align__(16) float g_B[HTOT_];
__device__ __align__(16) float g_agg[HTOT_];
__device__ __align__(16) float g_d2[E_];

__constant__ float CT8[8] = {1.f,  0.70710678118654752f, 0.f, -0.70710678118654752f,
                             -1.f, -0.70710678118654752f, 0.f,  0.70710678118654752f};
__constant__ float ST8[8] = {0.f,  0.70710678118654752f, 1.f,  0.70710678118654752f,
                             0.f, -0.70710678118654752f, -1.f, -0.70710678118654752f};

typedef unsigned long long ull;

__device__ __forceinline__ float silu_f(float x)    { return x / (1.f + __expf(-x)); }
__device__ __forceinline__ float sigmoid_f(float x) { return 1.f / (1.f + __expf(-x)); }

__device__ __forceinline__ ull pk2(float lo, float hi) {
    ull r; asm("mov.b64 %0,{%1,%2};" : "=l"(r) : "f"(lo), "f"(hi)); return r;
}
__device__ __forceinline__ void upk2(ull v, float& lo, float& hi) {
    asm("mov.b64 {%0,%1},%2;" : "=f"(lo), "=f"(hi) : "l"(v));
}
__device__ __forceinline__ ull f2fma(ull a, ull b, ull c) {
    ull d; asm("fma.rn.f32x2 %0,%1,%2,%3;" : "=l"(d) : "l"(a), "l"(b), "l"(c)); return d;
}
// tf32 destination is a b32 register per PTX ISA -> "=r" constraint.
__device__ __forceinline__ float tf32r(float x) {
    unsigned int y; asm("cvt.rna.tf32.f32 %0,%1;" : "=r"(y) : "f"(x));
    return __uint_as_float(y);
}

#define MMA_TF32(c, a, b) \
    asm volatile("mma.sync.aligned.m16n8k8.row.col.f32.tf32.tf32.f32 " \
        "{%0,%1,%2,%3}, {%4,%5,%6,%7}, {%8,%9}, {%0,%1,%2,%3};" \
        : "+f"((c)[0]), "+f"((c)[1]), "+f"((c)[2]), "+f"((c)[3]) \
        : "r"(__float_as_uint((a)[0])), "r"(__float_as_uint((a)[1])), \
          "r"(__float_as_uint((a)[2])), "r"(__float_as_uint((a)[3])), \
          "r"(__float_as_uint((b)[0])), "r"(__float_as_uint((b)[1])))

// ---------------------------------------------------------------------------
// Kernel 1: TimeConv on h.  8 nodes/block, 2 nodes per phase-B thread.
// ---------------------------------------------------------------------------
__global__ void __launch_bounds__(256, 2) k_time_h(const float* __restrict__ h,
                                                   const float* __restrict__ whr,
                                                   const float* __restrict__ whi) {
    extern __shared__ float sm[];
    float* sWr12 = sm;            // [i*64+o]*2 : (wr1, wr2)
    float* sWi12 = sm + 8192;     // (wi1, wi2)
    float* sWr0  = sm + 16384;    // wr0
    float* sxf   = sm + 20480;    // [8 slot][64 i][8]
    const int tid = threadIdx.x;

    for (int idx = tid; idx < 4096; idx += 256) {
        int base = idx * 3;                  // (i*64+o)*3
        sWr12[idx * 2]     = whr[base + 1];
        sWr12[idx * 2 + 1] = whr[base + 2];
        sWi12[idx * 2]     = whi[base + 1];
        sWi12[idx * 2 + 1] = whi[base + 2];
        sWr0[idx]          = whr[base];
    }

    const int grp = tid >> 6;
    const int l   = tid & 63;
    const int node0 = blockIdx.x * 8 + grp * 2;

    // Phase A: rfft per (node, channel=l)
#pragma unroll
    for (int pp = 0; pp < 2; ++pp) {
        int node = node0 + pp;
        float xv[8];
#pragma unroll
        for (int t = 0; t < 8; ++t) xv[t] = h[t * (BN_ * C_) + node * C_ + l];
        float xr0 = 0.f, xr1 = 0.f, xi1 = 0.f, xr2 = 0.f, xi2 = 0.f;
#pragma unroll
        for (int t = 0; t < 8; ++t) {
            xr0 += xv[t];
            xr1 += xv[t] * CT8[t];
            xi1 -= xv[t] * ST8[t];
            xr2 += xv[t] * CT8[(2 * t) & 7];
            xi2 -= xv[t] * ST8[(2 * t) & 7];
        }
        float* p = sxf + (grp * 2 + pp) * 512 + l * 8;
        p[0] = xr1;  p[1] = xr2;
        p[2] = xi1;  p[3] = xi2;
        p[4] = -xi1; p[5] = -xi2;
        p[6] = xr0;  p[7] = 0.f;
    }
    __syncthreads();

    // Phase B: complex mix for o = l, 2 nodes (128-bit shared loads)
    ull omrA = pk2(0.f, 0.f), omiA = omrA, omrB = omrA, omiB = omrA;
    float om0A = 0.f, om0B = 0.f;
    const float* xA = sxf + grp * 1024;
    const float* xB = xA + 512;
#pragma unroll 4
    for (int i = 0; i < 64; ++i) {
        ull wr12 = *(const ull*)(sWr12 + (i * 64 + l) * 2);
        ull wi12 = *(const ull*)(sWi12 + (i * 64 + l) * 2);
        float wr0 = sWr0[i * 64 + l];
        const float* pa = xA + i * 8;
        const float* pb = xB + i * 8;
        ulonglong2 va = *(const ulonglong2*)pa;       // (xra, xia)
        ull nxa = *(const ull*)(pa + 4);
        ulonglong2 vb = *(const ulonglong2*)pb;
        ull nxb = *(const ull*)(pb + 4);
        omrA = f2fma(va.x, wr12, omrA); omrA = f2fma(nxa, wi12, omrA);
        omiA = f2fma(va.x, wi12, omiA); omiA = f2fma(va.y, wr12, omiA);
        om0A = fmaf(pa[6], wr0, om0A);
        omrB = f2fma(vb.x, wr12, omrB); omrB = f2fma(nxb, wi12, omrB);
        omiB = f2fma(vb.x, wi12, omiB); omiB = f2fma(vb.y, wr12, omiB);
        om0B = fmaf(pb[6], wr0, om0B);
    }

    // Phase C: irfft + leaky residual
#pragma unroll
    for (int pp = 0; pp < 2; ++pp) {
        int node = node0 + pp;
        float or1, or2, oi1, oi2, o0;
        if (pp == 0) { upk2(omrA, or1, or2); upk2(omiA, oi1, oi2); o0 = om0A; }
        else         { upk2(omrB, or1, or2); upk2(omiB, oi1, oi2); o0 = om0B; }
#pragma unroll
        for (int t = 0; t < 8; ++t) {
            float val = o0
                + 2.f * (or1 * CT8[t]           - oi1 * ST8[t])
                + 2.f * (or2 * CT8[(2 * t) & 7] - oi2 * ST8[(2 * t) & 7]);
            val *= 0.125f;
            float lr = val > 0.f ? val : 0.2f * val;
            int off = t * (BN_ * C_) + node * C_ + l;
            g_hnew[off] = h[off] + lr;
        }
    }
}

// ---------------------------------------------------------------------------
// Kernel 2: TimeConvX on velocity
// ---------------------------------------------------------------------------
__global__ void k_time_v(const float* __restrict__ vel,
                         const float* __restrict__ wvr,
                         const float* __restrict__ wvi,
                         float* __restrict__ out) {
    int j = blockIdx.x * blockDim.x + threadIdx.x;
    if (j >= BN_ * 3) return;
    int b = j / 3, d = j - b * 3;
    float xv[8];
#pragma unroll
    for (int t = 0; t < 8; ++t) xv[t] = vel[b * (T_ * 3) + t * 3 + d];
    float xr0 = 0.f, xr1 = 0.f, xi1 = 0.f, xr2 = 0.f, xi2 = 0.f;
#pragma unroll
    for (int t = 0; t < 8; ++t) {
        xr0 += xv[t];
        xr1 += xv[t] * CT8[t];
        xi1 -= xv[t] * ST8[t];
        xr2 += xv[t] * CT8[(2 * t) & 7];
        xi2 -= xv[t] * ST8[(2 * t) & 7];
    }
    float w0r = wvr[0];
    float w1r = wvr[1], w1i = wvi[1];
    float w2r = wvr[2], w2i = wvi[2];
    float yr0 = xr0 * w0r;
    float yr1 = xr1 * w1r - xi1 * w1i;
    float yi1 = xr1 * w1i + xi1 * w1r;
    float yr2 = xr2 * w2r - xi2 * w2i;
    float yi2 = xr2 * w2i + xi2 * w2r;
#pragma unroll
    for (int t = 0; t < 8; ++t) {
        float val = 0.125f * (yr0
            + 2.f * (yr1 * CT8[t]           - yi1 * ST8[t])
            + 2.f * (yr2 * CT8[(2 * t) & 7] - yi2 * ST8[(2 * t) & 7]));
        out[b * (T_ * 3) + t * 3 + d] = xv[t] + val;
    }
}

// ---------------------------------------------------------------------------
// Kernel 3: per-base-edge squared distance
// ---------------------------------------------------------------------------
__global__ void k_d2(const float* __restrict__ x, const int* __restrict__ ei) {
    int e = blockIdx.x * blockDim.x + threadIdx.x;
    if (e >= E_) return;
    int r = ei[e];
    int c = ei[E_ + e];
    float dx = x[r * 3 + 0] - x[c * 3 + 0];
    float dy = x[r * 3 + 1] - x[c * 3 + 1];
    float dz = x[r * 3 + 2] - x[c * 3 + 2];
    g_d2[e] = dx * dx + dy * dy + dz * dz;
}

// ---------------------------------------------------------------------------
// Kernel 4: A/B precompute via tf32 mma.sync.
// M=64 nodes/block, N=128 (A|B), K=64. Warp (mh, nqq): 32m x 32n tile.
// Weights staged transposed [n][k], tf32-rounded; X tf32-rounded.
// ---------------------------------------------------------------------------
__global__ void __launch_bounds__(256, 4) k_ab(const float* __restrict__ We1,
                                               const float* __restrict__ be1) {
    extern __shared__ float sm[];
    float* sX  = sm;               // [64][68]  tf32
    float* sWt = sm + 4352;        // [128][68] tf32, [n][k]
    float* sb  = sm + 4352 + 8704; // [128]
    const int tid = threadIdx.x;

    // stage weights transposed+rounded: sWt[n][k]
    for (int idx = tid; idx < 8192; idx += 256) {
        int n = idx >> 6, k = idx & 63;
        float v = (n < 64) ? We1[k * 64 + n] : We1[(64 + k) * 64 + (n - 64)];
        sWt[n * 68 + k] = tf32r(v);
    }
    if (tid < 128) sb[tid] = (tid < 64) ? be1[tid] : 0.f;

    const int nb = blockIdx.x * 64;
    // stage X rounded + zero agg
    {
        int row = tid >> 2, l4 = tid & 3;
        const float4* hp = (const float4*)(g_hnew + (size_t)(nb + row) * 64 + l4 * 16);
        float4* agp = (float4*)(g_agg + (size_t)(nb + row) * 64 + l4 * 16);
        float* dst = sX + row * 68 + l4 * 16;
        float4 z = make_float4(0.f, 0.f, 0.f, 0.f);
#pragma unroll
        for (int jj = 0; jj < 4; ++jj) {
            float4 v = hp[jj];
            dst[4 * jj]     = tf32r(v.x);
            dst[4 * jj + 1] = tf32r(v.y);
            dst[4 * jj + 2] = tf32r(v.z);
            dst[4 * jj + 3] = tf32r(v.w);
            agp[jj] = z;
        }
    }
    __syncthreads();

    const int lane = tid & 31, w = tid >> 5;
    const int mh = w >> 2, nqq = w & 3;
    const int gId = lane >> 2, tig = lane & 3;
    const int mbase = mh * 32;
    const int nbase = nqq * 32;

    float acc[2][4][4];
#pragma unroll
    for (int mi = 0; mi < 2; ++mi)
#pragma unroll
        for (int nj = 0; nj < 4; ++nj) {
            float b0v = sb[nbase + nj * 8 + 2 * tig];
            float b1v = sb[nbase + nj * 8 + 2 * tig + 1];
            acc[mi][nj][0] = b0v; acc[mi][nj][1] = b1v;
            acc[mi][nj][2] = b0v; acc[mi][nj][3] = b1v;
        }

#pragma unroll
    for (int ki = 0; ki < 8; ++ki) {
        const int kb = ki * 8 + tig;
        float a[2][4], b[4][2];
#pragma unroll
        for (int mi = 0; mi < 2; ++mi) {
            const float* r0 = sX + (mbase + mi * 16 + gId) * 68;
            a[mi][0] = r0[kb];
            a[mi][1] = r0[8 * 68 + kb];
            a[mi][2] = r0[kb + 4];
            a[mi][3] = r0[8 * 68 + kb + 4];
        }
#pragma unroll
        for (int nj = 0; nj < 4; ++nj) {
            const float* bn = sWt + (nbase + nj * 8 + gId) * 68;
            b[nj][0] = bn[kb];
            b[nj][1] = bn[kb + 4];
        }
#pragma unroll
        for (int mi = 0; mi < 2; ++mi)
#pragma unroll
            for (int nj = 0; nj < 4; ++nj)
                MMA_TF32(acc[mi][nj], a[mi], b[nj]);
    }

    // store: rows mbase+mi*16+gId(+8), cols nbase+nj*8+2tig(+1)
#pragma unroll
    for (int mi = 0; mi < 2; ++mi)
#pragma unroll
        for (int half = 0; half < 2; ++half) {
            int node = nb + mbase + mi * 16 + gId + half * 8;
#pragma unroll
            for (int nj = 0; nj < 4; ++nj) {
                int col = nbase + nj * 8 + 2 * tig;
                float2 v = make_float2(acc[mi][nj][half * 2],
                                       acc[mi][nj][half * 2 + 1]);
                if (col < 64)
                    *(float2*)(g_A + (size_t)node * 64 + col) = v;
                else
                    *(float2*)(g_B + (size_t)node * 64 + (col - 64)) = v;
            }
        }
}

// ---------------------------------------------------------------------------
// Kernel 5: edge messages. 128 edges/block, 3 blocks/SM. tf32 mma phase 2.
// (unchanged from R13 — validated)
// ---------------------------------------------------------------------------
__global__ void __launch_bounds__(256, 3) k_edge(const int* __restrict__ ei,
                                                 const float* __restrict__ We1,
                                                 const float* __restrict__ We2,
                                                 const float* __restrict__ be2,
                                                 const float* __restrict__ Wg,
                                                 const float* __restrict__ bg) {
    extern __shared__ float sm[];
    float* sm1  = sm;                   // [128][68]  m1, tf32-rounded
    float* sW2t = sm + 8704;            // [64][68]  We2 transposed [n][k], tf32-rounded
    float* swl  = sm + 13056;           // [64]
    float* sg   = sm + 13120;           // [64]
    float* sb2  = sm + 13184;           // [64]
    int*   srb  = (int*)(sm + 13248);   // [128]
    float* sgp  = sm + 13376;           // [2][128] gate partials
    const int tid = threadIdx.x;

    for (int idx = tid; idx < 4096; idx += 256) {
        int k = idx >> 6, n = idx & 63;
        sW2t[n * 68 + k] = tf32r(We2[k * 64 + n]);
    }
    if (tid < 64) {
        swl[tid] = We1[128 * 64 + tid];
        sg[tid]  = Wg[tid];
        sb2[tid] = be2[tid];
    }
    __syncthreads();

    const int t  = blockIdx.x / 1250;
    const int jb = (blockIdx.x - t * 1250) * 128;

    // Phase 1: m1 = tf32(silu(A[rb] + B[cb] + d2*wl)) for 128 edges
    {
        const int eIdx = tid >> 2, l4 = tid & 3;
#pragma unroll
        for (int p = 0; p < 2; ++p) {
            int e = p * 64 + eIdx;
            int j = jb + e;
            int rb = t * BN_ + __ldg(ei + j);
            int cb = t * BN_ + __ldg(ei + E_ + j);
            if (l4 == 0) srb[e] = rb;
            float dd = g_d2[j];
            const float4* Ap = (const float4*)(g_A + (size_t)rb * 64 + l4 * 16);
            const float4* Bp = (const float4*)(g_B + (size_t)cb * 64 + l4 * 16);
            const float4* wl = (const float4*)(swl + l4 * 16);
            float4* dst = (float4*)(sm1 + e * 68 + l4 * 16);
#pragma unroll
            for (int jj = 0; jj < 4; ++jj) {
                float4 a = Ap[jj], b = Bp[jj], ww = wl[jj];
                float4 o;
                o.x = tf32r(silu_f(a.x + b.x + dd * ww.x));
                o.y = tf32r(silu_f(a.y + b.y + dd * ww.y));
                o.z = tf32r(silu_f(a.z + b.z + dd * ww.z));
                o.w = tf32r(silu_f(a.w + b.w + dd * ww.w));
                dst[jj] = o;
            }
        }
    }
    __syncthreads();

    // Phase 2: tf32 mma. warp w = (g2, nh): edges g2*32..+31, outputs nh*32..+31.
    const int lane = tid & 31, w = tid >> 5;
    const int g2 = w >> 1, nh = w & 1;
    const int gId = lane >> 2, tig = lane & 3;
    const int m0w = g2 * 32;
    const int nhb = nh * 32;

    float acc[2][4][4];
#pragma unroll
    for (int mi = 0; mi < 2; ++mi)
#pragma unroll
        for (int nj = 0; nj < 4; ++nj) {
            float b0v = sb2[nhb + nj * 8 + 2 * tig];
            float b1v = sb2[nhb + nj * 8 + 2 * tig + 1];
            acc[mi][nj][0] = b0v; acc[mi][nj][1] = b1v;
            acc[mi][nj][2] = b0v; acc[mi][nj][3] = b1v;
        }

#pragma unroll
    for (int ki = 0; ki < 8; ++ki) {
        const int kb = ki * 8 + tig;
        float a[2][4], b[4][2];
#pragma unroll
        for (int mi = 0; mi < 2; ++mi) {
            const float* r0 = sm1 + (m0w + mi * 16 + gId) * 68;
            a[mi][0] = r0[kb];
            a[mi][1] = r0[8 * 68 + kb];
            a[mi][2] = r0[kb + 4];
            a[mi][3] = r0[8 * 68 + kb + 4];
        }
#pragma unroll
        for (int nj = 0; nj < 4; ++nj) {
            const float* bn = sW2t + (nhb + nj * 8 + gId) * 68;
            b[nj][0] = bn[kb];
            b[nj][1] = bn[kb + 4];
        }
#pragma unroll
        for (int mi = 0; mi < 2; ++mi)
#pragma unroll
            for (int nj = 0; nj < 4; ++nj)
                MMA_TF32(acc[mi][nj], a[mi], b[nj]);
    }

    // Phase 3a: silu in place + partial gate dot (this warp's 32 n)
#pragma unroll
    for (int mi = 0; mi < 2; ++mi)
#pragma unroll
        for (int half = 0; half < 2; ++half) {
            int lm = m0w + mi * 16 + gId + half * 8;
            float d = 0.f;
#pragma unroll
            for (int nj = 0; nj < 4; ++nj) {
                int n0 = nhb + nj * 8 + 2 * tig;
                float s0 = silu_f(acc[mi][nj][half * 2]);
                float s1 = silu_f(acc[mi][nj][half * 2 + 1]);
                acc[mi][nj][half * 2]     = s0;
                acc[mi][nj][half * 2 + 1] = s1;
                d += s0 * sg[n0] + s1 * sg[n0 + 1];
            }
            d += __shfl_xor_sync(0xffffffffu, d, 1);
            d += __shfl_xor_sync(0xffffffffu, d, 2);
            if (tig == 0) sgp[nh * 128 + lm] = d;
        }
    __syncthreads();

    // Phase 3b: full gate, v2 REDs for this warp's n-half
    const float bgv = __ldg(bg);
#pragma unroll
    for (int mi = 0; mi < 2; ++mi)
#pragma unroll
        for (int half = 0; half < 2; ++half) {
            int lm = m0w + mi * 16 + gId + half * 8;
            float gate = sigmoid_f(sgp[lm] + sgp[128 + lm] + bgv);
            float* ag = g_agg + (size_t)srb[lm] * 64;
#pragma unroll
            for (int nj = 0; nj < 4; ++nj) {
                int n0 = nhb + nj * 8 + 2 * tig;
                asm volatile("red.global.add.v2.f32 [%0], {%1,%2};" ::
                    "l"(ag + n0),
                    "f"(gate * acc[mi][nj][half * 2]),
                    "f"(gate * acc[mi][nj][half * 2 + 1]) : "memory");
            }
        }
}

// ---------------------------------------------------------------------------
// Kernel 6: node update via two tf32 mma GEMMs.
// Warp (mh, nqq): 32m x 16n tile. Layer1 K=128, layer2 K=64.
// Residual reloads h from g_hnew (full precision).
// ---------------------------------------------------------------------------
__global__ void __launch_bounds__(256, 2) k_node(const float* __restrict__ Wn1,
                                                 const float* __restrict__ bn1,
                                                 const float* __restrict__ Wn2,
                                                 const float* __restrict__ bn2,
                                                 float* __restrict__ out) {
    extern __shared__ float sm[];
    float* sX   = sm;            // [64][132] tf32 [h | agg]
    float* sW1t = sm + 8448;     // [64 n][128 k] stride 132, tf32
    float* sU   = sm + 16896;    // [64][68] tf32
    float* sW2t = sm + 21248;    // [64 n][64 k] stride 68, tf32
    float* sb1  = sm + 25600;    // [64]
    float* sb2  = sm + 25664;    // [64]
    const int tid = threadIdx.x;

    for (int idx = tid; idx < 8192; idx += 256) {
        int n = idx & 63, k = idx >> 6;
        sW1t[n * 132 + k] = tf32r(Wn1[k * 64 + n]);
    }
    for (int idx = tid; idx < 4096; idx += 256) {
        int n = idx & 63, k = idx >> 6;
        sW2t[n * 68 + k] = tf32r(Wn2[k * 64 + n]);
    }
    if (tid < 64) { sb1[tid] = bn1[tid]; sb2[tid] = bn2[tid]; }

    const int nb = blockIdx.x * 64;
    {
        int row = tid >> 2, l4 = tid & 3;
        const float4* hp = (const float4*)(g_hnew + (size_t)(nb + row) * 64 + l4 * 16);
        const float4* gp = (const float4*)(g_agg  + (size_t)(nb + row) * 64 + l4 * 16);
        float* dh = sX + row * 132 + l4 * 16;
        float* da = sX + row * 132 + 64 + l4 * 16;
#pragma unroll
        for (int jj = 0; jj < 4; ++jj) {
            float4 v = hp[jj];
            dh[4*jj] = tf32r(v.x); dh[4*jj+1] = tf32r(v.y);
            dh[4*jj+2] = tf32r(v.z); dh[4*jj+3] = tf32r(v.w);
            float4 a = gp[jj];
            da[4*jj] = tf32r(a.x); da[4*jj+1] = tf32r(a.y);
            da[4*jj+2] = tf32r(a.z); da[4*jj+3] = tf32r(a.w);
        }
    }
    __syncthreads();

    const int lane = tid & 31, w = tid >> 5;
    const int mh = w >> 2, nqq = w & 3;
    const int gId = lane >> 2, tig = lane & 3;
    const int mbase = mh * 32;
    const int nbase = nqq * 16;

    // ---- layer 1 (K = 128) ----
    float acc[2][2][4];
#pragma unroll
    for (int mi = 0; mi < 2; ++mi)
#pragma unroll
        for (int nj = 0; nj < 2; ++nj) {
            float b0v = sb1[nbase + nj * 8 + 2 * tig];
            float b1v = sb1[nbase + nj * 8 + 2 * tig + 1];
            acc[mi][nj][0] = b0v; acc[mi][nj][1] = b1v;
            acc[mi][nj][2] = b0v; acc[mi][nj][3] = b1v;
        }
#pragma unroll
    for (int ki = 0; ki < 16; ++ki) {
        const int kb = ki * 8 + tig;
        float a[2][4], b[2][2];
#pragma unroll
        for (int mi = 0; mi < 2; ++mi) {
            const float* r0 = sX + (mbase + mi * 16 + gId) * 132;
            a[mi][0] = r0[kb];
            a[mi][1] = r0[8 * 132 + kb];
            a[mi][2] = r0[kb + 4];
            a[mi][3] = r0[8 * 132 + kb + 4];
        }
#pragma unroll
        for (int nj = 0; nj < 2; ++nj) {
            const float* bn = sW1t + (nbase + nj * 8 + gId) * 132;
            b[nj][0] = bn[kb];
            b[nj][1] = bn[kb + 4];
        }
#pragma unroll
        for (int mi = 0; mi < 2; ++mi)
#pragma unroll
            for (int nj = 0; nj < 2; ++nj)
                MMA_TF32(acc[mi][nj], a[mi], b[nj]);
    }
    // silu -> sU (tf32 rounded)
#pragma unroll
    for (int mi = 0; mi < 2; ++mi)
#pragma unroll
        for (int half = 0; half < 2; ++half) {
            int row = mbase + mi * 16 + gId + half * 8;
#pragma unroll
            for (int nj = 0; nj < 2; ++nj) {
                int col = nbase + nj * 8 + 2 * tig;
                float2 v = make_float2(
                    tf32r(silu_f(acc[mi][nj][half * 2])),
                    tf32r(silu_f(acc[mi][nj][half * 2 + 1])));
                *(float2*)(sU + row * 68 + col) = v;
            }
        }
    __syncthreads();

    // ---- layer 2 (K = 64) ----
    float acc2[2][2][4];
#pragma unroll
    for (int mi = 0; mi < 2; ++mi)
#pragma unroll
        for (int nj = 0; nj < 2; ++nj) {
            float b0v = sb2[nbase + nj * 8 + 2 * tig];
            float b1v = sb2[nbase + nj * 8 + 2 * tig + 1];
            acc2[mi][nj][0] = b0v; acc2[mi][nj][1] = b1v;
            acc2[mi][nj][2] = b0v; acc2[mi][nj][3] = b1v;
        }
#pragma unroll
    for (int ki = 0; ki < 8; ++ki) {
        const int kb = ki * 8 + tig;
        float a[2][4], b[2][2];
#pragma unroll
        for (int mi = 0; mi < 2; ++mi) {
            const float* r0 = sU + (mbase + mi * 16 + gId) * 68;
            a[mi][0] = r0[kb];
            a[mi][1] = r0[8 * 68 + kb];
            a[mi][2] = r0[kb + 4];
            a[mi][3] = r0[8 * 68 + kb + 4];
        }
#pragma unroll
        for (int nj = 0; nj < 2; ++nj) {
            const float* bn = sW2t + (nbase + nj * 8 + gId) * 68;
            b[nj][0] = bn[kb];
            b[nj][1] = bn[kb + 4];
        }
#pragma unroll
        for (int mi = 0; mi < 2; ++mi)
#pragma unroll
            for (int nj = 0; nj < 2; ++nj)
                MMA_TF32(acc2[mi][nj], a[mi], b[nj]);
    }

    // residual (full-precision h from g_hnew) + store
#pragma unroll
    for (int mi = 0; mi < 2; ++mi)
#pragma unroll
        for (int half = 0; half < 2; ++half) {
            int row = mbase + mi * 16 + gId + half * 8;
            int node = nb + row;
#pragma unroll
            for (int nj = 0; nj < 2; ++nj) {
                int col = nbase + nj * 8 + 2 * tig;
                float2 hv = *(const float2*)(g_hnew + (size_t)node * 64 + col);
                float2 v = make_float2(acc2[mi][nj][half * 2] + hv.x,
                                       acc2[mi][nj][half * 2 + 1] + hv.y);
                *(float2*)(out + (size_t)node * 64 + col) = v;
            }
        }
}

// ---------------------------------------------------------------------------
extern "C" void kernel_launch(void* const* d_in, const int* in_sizes, int n_in,
                              void* d_out, int out_size) {
    const float* h   = (const float*)d_in[0];
    const float* x   = (const float*)d_in[1];
    const float* vel = (const float*)d_in[2];
    const int*   ei  = (const int*)d_in[3];
    const float* whr = (const float*)d_in[4];
    const float* whi = (const float*)d_in[5];
    const float* wvr = (const float*)d_in[6];
    const float* wvi = (const float*)d_in[7];
    const float* We1 = (const float*)d_in[8];
    const float* be1 = (const float*)d_in[9];
    const float* We2 = (const float*)d_in[10];
    const float* be2 = (const float*)d_in[11];
    const float* Wg  = (const float*)d_in[12];
    const float* bg  = (const float*)d_in[13];
    const float* Wn1 = (const float*)d_in[14];
    const float* bn1 = (const float*)d_in[15];
    const float* Wn2 = (const float*)d_in[16];
    const float* bn2 = (const float*)d_in[17];
    float* out = (float*)d_out;

    (void)in_sizes; (void)n_in; (void)out_size;

    const int smem_h    = 24576 * 4;  // 98304
    const int smem_ab   = 13184 * 4;  // 52736
    const int smem_edge = 13632 * 4;  // 54528
    const int smem_node = 25728 * 4;  // 102912
    cudaFuncSetAttribute(k_time_h, cudaFuncAttributeMaxDynamicSharedMemorySize, smem_h);
    cudaFuncSetAttribute(k_ab,     cudaFuncAttributeMaxDynamicSharedMemorySize, smem_ab);
    cudaFuncSetAttribute(k_edge,   cudaFuncAttributeMaxDynamicSharedMemorySize, smem_edge);
    cudaFuncSetAttribute(k_node,   cudaFuncAttributeMaxDynamicSharedMemorySize, smem_node);

    // k_edge stays 4th so ncu captures it.
    k_d2<<<(E_ + 255) / 256, 256>>>(x, ei);
    k_time_h<<<1250, 256, smem_h>>>(h, whr, whi);
    k_ab<<<1250, 256, smem_ab>>>(We1, be1);
    k_edge<<<10000, 256, smem_edge>>>(ei, We1, We2, be2, Wg, bg);
    k_time_v<<<(BN_ * 3 + 255) / 256, 256>>>(vel, wvr, wvi, out + HTOT_);
    k_node<<<1250, 256, smem_node>>>(Wn1, bn1, Wn2, bn2, out);
}

// round 16
// speedup vs baseline: 1.2316x; 1.0037x over previous
#include <cuda_runtime.h>

// Problem constants
#define BN_   10000
#define T_    8
#define C_    64
#define NM_   3
#define E_    160000
#define NTOT_ (T_ * BN_)        // 80000 node-rows
#define HTOT_ (NTOT_ * C_)      // 5,120,000

// Scratch (device globals: allocation-free rule)
__device__ __align__(16) float g_hnew[HTOT_];
__device__ __align__(16) float g_A[HTOT_];
__device__ __align__(16) float g_B[HTOT_];
__device__ __align__(16) float g_agg[HTOT_];
__device__ __align__(16) float g_d2[E_];

__constant__ float CT8[8] = {1.f,  0.70710678118654752f, 0.f, -0.70710678118654752f,
                             -1.f, -0.70710678118654752f, 0.f,  0.70710678118654752f};
__constant__ float ST8[8] = {0.f,  0.70710678118654752f, 1.f,  0.70710678118654752f,
                             0.f, -0.70710678118654752f, -1.f, -0.70710678118654752f};

typedef unsigned long long ull;

__device__ __forceinline__ float silu_f(float x)    { return x / (1.f + __expf(-x)); }
__device__ __forceinline__ float sigmoid_f(float x) { return 1.f / (1.f + __expf(-x)); }

__device__ __forceinline__ ull pk2(float lo, float hi) {
    ull r; asm("mov.b64 %0,{%1,%2};" : "=l"(r) : "f"(lo), "f"(hi)); return r;
}
__device__ __forceinline__ void upk2(ull v, float& lo, float& hi) {
    asm("mov.b64 {%0,%1},%2;" : "=f"(lo), "=f"(hi) : "l"(v));
}
__device__ __forceinline__ ull f2fma(ull a, ull b, ull c) {
    ull d; asm("fma.rn.f32x2 %0,%1,%2,%3;" : "=l"(d) : "l"(a), "l"(b), "l"(c)); return d;
}
// tf32 destination is a b32 register per PTX ISA -> "=r" constraint.
__device__ __forceinline__ float tf32r(float x) {
    unsigned int y; asm("cvt.rna.tf32.f32 %0,%1;" : "=r"(y) : "f"(x));
    return __uint_as_float(y);
}

#define MMA_TF32(c, a, b) \
    asm volatile("mma.sync.aligned.m16n8k8.row.col.f32.tf32.tf32.f32 " \
        "{%0,%1,%2,%3}, {%4,%5,%6,%7}, {%8,%9}, {%0,%1,%2,%3};" \
        : "+f"((c)[0]), "+f"((c)[1]), "+f"((c)[2]), "+f"((c)[3]) \
        : "r"(__float_as_uint((a)[0])), "r"(__float_as_uint((a)[1])), \
          "r"(__float_as_uint((a)[2])), "r"(__float_as_uint((a)[3])), \
          "r"(__float_as_uint((b)[0])), "r"(__float_as_uint((b)[1])))

// ---------------------------------------------------------------------------
// Kernel 1: TimeConv on h.  8 nodes/block, 2 nodes per phase-B thread.
// ---------------------------------------------------------------------------
__global__ void __launch_bounds__(256, 2) k_time_h(const float* __restrict__ h,
                                                   const float* __restrict__ whr,
                                                   const float* __restrict__ whi) {
    extern __shared__ float sm[];
    float* sWr12 = sm;            // [i*64+o]*2 : (wr1, wr2)
    float* sWi12 = sm + 8192;     // (wi1, wi2)
    float* sWr0  = sm + 16384;    // wr0
    float* sxf   = sm + 20480;    // [8 slot][64 i][8]
    const int tid = threadIdx.x;

    for (int idx = tid; idx < 4096; idx += 256) {
        int base = idx * 3;                  // (i*64+o)*3
        sWr12[idx * 2]     = whr[base + 1];
        sWr12[idx * 2 + 1] = whr[base + 2];
        sWi12[idx * 2]     = whi[base + 1];
        sWi12[idx * 2 + 1] = whi[base + 2];
        sWr0[idx]          = whr[base];
    }

    const int grp = tid >> 6;
    const int l   = tid & 63;
    const int node0 = blockIdx.x * 8 + grp * 2;

    // Phase A: rfft per (node, channel=l)
#pragma unroll
    for (int pp = 0; pp < 2; ++pp) {
        int node = node0 + pp;
        float xv[8];
#pragma unroll
        for (int t = 0; t < 8; ++t) xv[t] = h[t * (BN_ * C_) + node * C_ + l];
        float xr0 = 0.f, xr1 = 0.f, xi1 = 0.f, xr2 = 0.f, xi2 = 0.f;
#pragma unroll
        for (int t = 0; t < 8; ++t) {
            xr0 += xv[t];
            xr1 += xv[t] * CT8[t];
            xi1 -= xv[t] * ST8[t];
            xr2 += xv[t] * CT8[(2 * t) & 7];
            xi2 -= xv[t] * ST8[(2 * t) & 7];
        }
        float* p = sxf + (grp * 2 + pp) * 512 + l * 8;
        p[0] = xr1;  p[1] = xr2;
        p[2] = xi1;  p[3] = xi2;
        p[4] = -xi1; p[5] = -xi2;
        p[6] = xr0;  p[7] = 0.f;
    }
    __syncthreads();

    // Phase B: complex mix for o = l, 2 nodes (128-bit shared loads)
    ull omrA = pk2(0.f, 0.f), omiA = omrA, omrB = omrA, omiB = omrA;
    float om0A = 0.f, om0B = 0.f;
    const float* xA = sxf + grp * 1024;
    const float* xB = xA + 512;
#pragma unroll 4
    for (int i = 0; i < 64; ++i) {
        ull wr12 = *(const ull*)(sWr12 + (i * 64 + l) * 2);
        ull wi12 = *(const ull*)(sWi12 + (i * 64 + l) * 2);
        float wr0 = sWr0[i * 64 + l];
        const float* pa = xA + i * 8;
        const float* pb = xB + i * 8;
        ulonglong2 va = *(const ulonglong2*)pa;       // (xra, xia)
        ull nxa = *(const ull*)(pa + 4);
        ulonglong2 vb = *(const ulonglong2*)pb;
        ull nxb = *(const ull*)(pb + 4);
        omrA = f2fma(va.x, wr12, omrA); omrA = f2fma(nxa, wi12, omrA);
        omiA = f2fma(va.x, wi12, omiA); omiA = f2fma(va.y, wr12, omiA);
        om0A = fmaf(pa[6], wr0, om0A);
        omrB = f2fma(vb.x, wr12, omrB); omrB = f2fma(nxb, wi12, omrB);
        omiB = f2fma(vb.x, wi12, omiB); omiB = f2fma(vb.y, wr12, omiB);
        om0B = fmaf(pb[6], wr0, om0B);
    }

    // Phase C: irfft + leaky residual
#pragma unroll
    for (int pp = 0; pp < 2; ++pp) {
        int node = node0 + pp;
        float or1, or2, oi1, oi2, o0;
        if (pp == 0) { upk2(omrA, or1, or2); upk2(omiA, oi1, oi2); o0 = om0A; }
        else         { upk2(omrB, or1, or2); upk2(omiB, oi1, oi2); o0 = om0B; }
#pragma unroll
        for (int t = 0; t < 8; ++t) {
            float val = o0
                + 2.f * (or1 * CT8[t]           - oi1 * ST8[t])
                + 2.f * (or2 * CT8[(2 * t) & 7] - oi2 * ST8[(2 * t) & 7]);
            val *= 0.125f;
            float lr = val > 0.f ? val : 0.2f * val;
            int off = t * (BN_ * C_) + node * C_ + l;
            g_hnew[off] = h[off] + lr;
        }
    }
}

// ---------------------------------------------------------------------------
// Kernel 2: TimeConvX on velocity
// ---------------------------------------------------------------------------
__global__ void k_time_v(const float* __restrict__ vel,
                         const float* __restrict__ wvr,
                         const float* __restrict__ wvi,
                         float* __restrict__ out) {
    int j = blockIdx.x * blockDim.x + threadIdx.x;
    if (j >= BN_ * 3) return;
    int b = j / 3, d = j - b * 3;
    float xv[8];
#pragma unroll
    for (int t = 0; t < 8; ++t) xv[t] = vel[b * (T_ * 3) + t * 3 + d];
    float xr0 = 0.f, xr1 = 0.f, xi1 = 0.f, xr2 = 0.f, xi2 = 0.f;
#pragma unroll
    for (int t = 0; t < 8; ++t) {
        xr0 += xv[t];
        xr1 += xv[t] * CT8[t];
        xi1 -= xv[t] * ST8[t];
        xr2 += xv[t] * CT8[(2 * t) & 7];
        xi2 -= xv[t] * ST8[(2 * t) & 7];
    }
    float w0r = wvr[0];
    float w1r = wvr[1], w1i = wvi[1];
    float w2r = wvr[2], w2i = wvi[2];
    float yr0 = xr0 * w0r;
    float yr1 = xr1 * w1r - xi1 * w1i;
    float yi1 = xr1 * w1i + xi1 * w1r;
    float yr2 = xr2 * w2r - xi2 * w2i;
    float yi2 = xr2 * w2i + xi2 * w2r;
#pragma unroll
    for (int t = 0; t < 8; ++t) {
        float val = 0.125f * (yr0
            + 2.f * (yr1 * CT8[t]           - yi1 * ST8[t])
            + 2.f * (yr2 * CT8[(2 * t) & 7] - yi2 * ST8[(2 * t) & 7]));
        out[b * (T_ * 3) + t * 3 + d] = xv[t] + val;
    }
}

// ---------------------------------------------------------------------------
// Kernel 3: per-base-edge squared distance
// ---------------------------------------------------------------------------
__global__ void k_d2(const float* __restrict__ x, const int* __restrict__ ei) {
    int e = blockIdx.x * blockDim.x + threadIdx.x;
    if (e >= E_) return;
    int r = ei[e];
    int c = ei[E_ + e];
    float dx = x[r * 3 + 0] - x[c * 3 + 0];
    float dy = x[r * 3 + 1] - x[c * 3 + 1];
    float dz = x[r * 3 + 2] - x[c * 3 + 2];
    g_d2[e] = dx * dx + dy * dy + dz * dz;
}

// ---------------------------------------------------------------------------
// Kernel 4: A/B precompute via tf32 mma.sync.
// M=64 nodes/block, N=128 (A|B), K=64. Warp (mh, nqq): 32m x 32n tile.
// Weights staged transposed [n][k], tf32-rounded; X tf32-rounded.
// ---------------------------------------------------------------------------
__global__ void __launch_bounds__(256, 4) k_ab(const float* __restrict__ We1,
                                               const float* __restrict__ be1) {
    extern __shared__ float sm[];
    float* sX  = sm;               // [64][68]  tf32
    float* sWt = sm + 4352;        // [128][68] tf32, [n][k]
    float* sb  = sm + 4352 + 8704; // [128]
    const int tid = threadIdx.x;

    // stage weights transposed+rounded: sWt[n][k]
    for (int idx = tid; idx < 8192; idx += 256) {
        int n = idx >> 6, k = idx & 63;
        float v = (n < 64) ? We1[k * 64 + n] : We1[(64 + k) * 64 + (n - 64)];
        sWt[n * 68 + k] = tf32r(v);
    }
    if (tid < 128) sb[tid] = (tid < 64) ? be1[tid] : 0.f;

    const int nb = blockIdx.x * 64;
    // stage X rounded + zero agg
    {
        int row = tid >> 2, l4 = tid & 3;
        const float4* hp = (const float4*)(g_hnew + (size_t)(nb + row) * 64 + l4 * 16);
        float4* agp = (float4*)(g_agg + (size_t)(nb + row) * 64 + l4 * 16);
        float* dst = sX + row * 68 + l4 * 16;
        float4 z = make_float4(0.f, 0.f, 0.f, 0.f);
#pragma unroll
        for (int jj = 0; jj < 4; ++jj) {
            float4 v = hp[jj];
            dst[4 * jj]     = tf32r(v.x);
            dst[4 * jj + 1] = tf32r(v.y);
            dst[4 * jj + 2] = tf32r(v.z);
            dst[4 * jj + 3] = tf32r(v.w);
            agp[jj] = z;
        }
    }
    __syncthreads();

    const int lane = tid & 31, w = tid >> 5;
    const int mh = w >> 2, nqq = w & 3;
    const int gId = lane >> 2, tig = lane & 3;
    const int mbase = mh * 32;
    const int nbase = nqq * 32;

    float acc[2][4][4];
#pragma unroll
    for (int mi = 0; mi < 2; ++mi)
#pragma unroll
        for (int nj = 0; nj < 4; ++nj) {
            float b0v = sb[nbase + nj * 8 + 2 * tig];
            float b1v = sb[nbase + nj * 8 + 2 * tig + 1];
            acc[mi][nj][0] = b0v; acc[mi][nj][1] = b1v;
            acc[mi][nj][2] = b0v; acc[mi][nj][3] = b1v;
        }

#pragma unroll
    for (int ki = 0; ki < 8; ++ki) {
        const int kb = ki * 8 + tig;
        float a[2][4], b[4][2];
#pragma unroll
        for (int mi = 0; mi < 2; ++mi) {
            const float* r0 = sX + (mbase + mi * 16 + gId) * 68;
            a[mi][0] = r0[kb];
            a[mi][1] = r0[8 * 68 + kb];
            a[mi][2] = r0[kb + 4];
            a[mi][3] = r0[8 * 68 + kb + 4];
        }
#pragma unroll
        for (int nj = 0; nj < 4; ++nj) {
            const float* bn = sWt + (nbase + nj * 8 + gId) * 68;
            b[nj][0] = bn[kb];
            b[nj][1] = bn[kb + 4];
        }
#pragma unroll
        for (int mi = 0; mi < 2; ++mi)
#pragma unroll
            for (int nj = 0; nj < 4; ++nj)
                MMA_TF32(acc[mi][nj], a[mi], b[nj]);
    }

    // store: rows mbase+mi*16+gId(+8), cols nbase+nj*8+2tig(+1)
#pragma unroll
    for (int mi = 0; mi < 2; ++mi)
#pragma unroll
        for (int half = 0; half < 2; ++half) {
            int node = nb + mbase + mi * 16 + gId + half * 8;
#pragma unroll
            for (int nj = 0; nj < 4; ++nj) {
                int col = nbase + nj * 8 + 2 * tig;
                float2 v = make_float2(acc[mi][nj][half * 2],
                                       acc[mi][nj][half * 2 + 1]);
                if (col < 64)
                    *(float2*)(g_A + (size_t)node * 64 + col) = v;
                else
                    *(float2*)(g_B + (size_t)node * 64 + (col - 64)) = v;
            }
        }
}

// ---------------------------------------------------------------------------
// Kernel 5: edge messages. 128 edges/block, 3 blocks/SM. tf32 mma phase 2.
// (unchanged from R13 — validated)
// ---------------------------------------------------------------------------
__global__ void __launch_bounds__(256, 3) k_edge(const int* __restrict__ ei,
                                                 const float* __restrict__ We1,
                                                 const float* __restrict__ We2,
                                                 const float* __restrict__ be2,
                                                 const float* __restrict__ Wg,
                                                 const float* __restrict__ bg) {
    extern __shared__ float sm[];
    float* sm1  = sm;                   // [128][68]  m1, tf32-rounded
    float* sW2t = sm + 8704;            // [64][68]  We2 transposed [n][k], tf32-rounded
    float* swl  = sm + 13056;           // [64]
    float* sg   = sm + 13120;           // [64]
    float* sb2  = sm + 13184;           // [64]
    int*   srb  = (int*)(sm + 13248);   // [128]
    float* sgp  = sm + 13376;           // [2][128] gate partials
    const int tid = threadIdx.x;

    for (int idx = tid; idx < 4096; idx += 256) {
        int k = idx >> 6, n = idx & 63;
        sW2t[n * 68 + k] = tf32r(We2[k * 64 + n]);
    }
    if (tid < 64) {
        swl[tid] = We1[128 * 64 + tid];
        sg[tid]  = Wg[tid];
        sb2[tid] = be2[tid];
    }
    __syncthreads();

    const int t  = blockIdx.x / 1250;
    const int jb = (blockIdx.x - t * 1250) * 128;

    // Phase 1: m1 = tf32(silu(A[rb] + B[cb] + d2*wl)) for 128 edges
    {
        const int eIdx = tid >> 2, l4 = tid & 3;
#pragma unroll
        for (int p = 0; p < 2; ++p) {
            int e = p * 64 + eIdx;
            int j = jb + e;
            int rb = t * BN_ + __ldg(ei + j);
            int cb = t * BN_ + __ldg(ei + E_ + j);
            if (l4 == 0) srb[e] = rb;
            float dd = g_d2[j];
            const float4* Ap = (const float4*)(g_A + (size_t)rb * 64 + l4 * 16);
            const float4* Bp = (const float4*)(g_B + (size_t)cb * 64 + l4 * 16);
            const float4* wl = (const float4*)(swl + l4 * 16);
            float4* dst = (float4*)(sm1 + e * 68 + l4 * 16);
#pragma unroll
            for (int jj = 0; jj < 4; ++jj) {
                float4 a = Ap[jj], b = Bp[jj], ww = wl[jj];
                float4 o;
                o.x = tf32r(silu_f(a.x + b.x + dd * ww.x));
                o.y = tf32r(silu_f(a.y + b.y + dd * ww.y));
                o.z = tf32r(silu_f(a.z + b.z + dd * ww.z));
                o.w = tf32r(silu_f(a.w + b.w + dd * ww.w));
                dst[jj] = o;
            }
        }
    }
    __syncthreads();

    // Phase 2: tf32 mma. warp w = (g2, nh): edges g2*32..+31, outputs nh*32..+31.
    const int lane = tid & 31, w = tid >> 5;
    const int g2 = w >> 1, nh = w & 1;
    const int gId = lane >> 2, tig = lane & 3;
    const int m0w = g2 * 32;
    const int nhb = nh * 32;

    float acc[2][4][4];
#pragma unroll
    for (int mi = 0; mi < 2; ++mi)
#pragma unroll
        for (int nj = 0; nj < 4; ++nj) {
            float b0v = sb2[nhb + nj * 8 + 2 * tig];
            float b1v = sb2[nhb + nj * 8 + 2 * tig + 1];
            acc[mi][nj][0] = b0v; acc[mi][nj][1] = b1v;
            acc[mi][nj][2] = b0v; acc[mi][nj][3] = b1v;
        }

#pragma unroll
    for (int ki = 0; ki < 8; ++ki) {
        const int kb = ki * 8 + tig;
        float a[2][4], b[4][2];
#pragma unroll
        for (int mi = 0; mi < 2; ++mi) {
            const float* r0 = sm1 + (m0w + mi * 16 + gId) * 68;
            a[mi][0] = r0[kb];
            a[mi][1] = r0[8 * 68 + kb];
            a[mi][2] = r0[kb + 4];
            a[mi][3] = r0[8 * 68 + kb + 4];
        }
#pragma unroll
        for (int nj = 0; nj < 4; ++nj) {
            const float* bn = sW2t + (nhb + nj * 8 + gId) * 68;
            b[nj][0] = bn[kb];
            b[nj][1] = bn[kb + 4];
        }
#pragma unroll
        for (int mi = 0; mi < 2; ++mi)
#pragma unroll
            for (int nj = 0; nj < 4; ++nj)
                MMA_TF32(acc[mi][nj], a[mi], b[nj]);
    }

    // Phase 3a: silu in place + partial gate dot (this warp's 32 n)
#pragma unroll
    for (int mi = 0; mi < 2; ++mi)
#pragma unroll
        for (int half = 0; half < 2; ++half) {
            int lm = m0w + mi * 16 + gId + half * 8;
            float d = 0.f;
#pragma unroll
            for (int nj = 0; nj < 4; ++nj) {
                int n0 = nhb + nj * 8 + 2 * tig;
                float s0 = silu_f(acc[mi][nj][half * 2]);
                float s1 = silu_f(acc[mi][nj][half * 2 + 1]);
                acc[mi][nj][half * 2]     = s0;
                acc[mi][nj][half * 2 + 1] = s1;
                d += s0 * sg[n0] + s1 * sg[n0 + 1];
            }
            d += __shfl_xor_sync(0xffffffffu, d, 1);
            d += __shfl_xor_sync(0xffffffffu, d, 2);
            if (tig == 0) sgp[nh * 128 + lm] = d;
        }
    __syncthreads();

    // Phase 3b: full gate, v2 REDs for this warp's n-half
    const float bgv = __ldg(bg);
#pragma unroll
    for (int mi = 0; mi < 2; ++mi)
#pragma unroll
        for (int half = 0; half < 2; ++half) {
            int lm = m0w + mi * 16 + gId + half * 8;
            float gate = sigmoid_f(sgp[lm] + sgp[128 + lm] + bgv);
            float* ag = g_agg + (size_t)srb[lm] * 64;
#pragma unroll
            for (int nj = 0; nj < 4; ++nj) {
                int n0 = nhb + nj * 8 + 2 * tig;
                asm volatile("red.global.add.v2.f32 [%0], {%1,%2};" ::
                    "l"(ag + n0),
                    "f"(gate * acc[mi][nj][half * 2]),
                    "f"(gate * acc[mi][nj][half * 2 + 1]) : "memory");
            }
        }
}

// ---------------------------------------------------------------------------
// Kernel 6: node update via two tf32 mma GEMMs.
// Warp (mh, nqq): 32m x 16n tile. Layer1 K=128, layer2 K=64.
// Residual reloads h from g_hnew (full precision).
// ---------------------------------------------------------------------------
__global__ void __launch_bounds__(256, 2) k_node(const float* __restrict__ Wn1,
                                                 const float* __restrict__ bn1,
                                                 const float* __restrict__ Wn2,
                                                 const float* __restrict__ bn2,
                                                 float* __restrict__ out) {
    extern __shared__ float sm[];
    float* sX   = sm;            // [64][132] tf32 [h | agg]
    float* sW1t = sm + 8448;     // [64 n][128 k] stride 132, tf32
    float* sU   = sm + 16896;    // [64][68] tf32
    float* sW2t = sm + 21248;    // [64 n][64 k] stride 68, tf32
    float* sb1  = sm + 25600;    // [64]
    float* sb2  = sm + 25664;    // [64]
    const int tid = threadIdx.x;

    for (int idx = tid; idx < 8192; idx += 256) {
        int n = idx & 63, k = idx >> 6;
        sW1t[n * 132 + k] = tf32r(Wn1[k * 64 + n]);
    }
    for (int idx = tid; idx < 4096; idx += 256) {
        int n = idx & 63, k = idx >> 6;
        sW2t[n * 68 + k] = tf32r(Wn2[k * 64 + n]);
    }
    if (tid < 64) { sb1[tid] = bn1[tid]; sb2[tid] = bn2[tid]; }

    const int nb = blockIdx.x * 64;
    {
        int row = tid >> 2, l4 = tid & 3;
        const float4* hp = (const float4*)(g_hnew + (size_t)(nb + row) * 64 + l4 * 16);
        const float4* gp = (const float4*)(g_agg  + (size_t)(nb + row) * 64 + l4 * 16);
        float* dh = sX + row * 132 + l4 * 16;
        float* da = sX + row * 132 + 64 + l4 * 16;
#pragma unroll
        for (int jj = 0; jj < 4; ++jj) {
            float4 v = hp[jj];
            dh[4*jj] = tf32r(v.x); dh[4*jj+1] = tf32r(v.y);
            dh[4*jj+2] = tf32r(v.z); dh[4*jj+3] = tf32r(v.w);
            float4 a = gp[jj];
            da[4*jj] = tf32r(a.x); da[4*jj+1] = tf32r(a.y);
            da[4*jj+2] = tf32r(a.z); da[4*jj+3] = tf32r(a.w);
        }
    }
    __syncthreads();

    const int lane = tid & 31, w = tid >> 5;
    const int mh = w >> 2, nqq = w & 3;
    const int gId = lane >> 2, tig = lane & 3;
    const int mbase = mh * 32;
    const int nbase = nqq * 16;

    // ---- layer 1 (K = 128) ----
    float acc[2][2][4];
#pragma unroll
    for (int mi = 0; mi < 2; ++mi)
#pragma unroll
        for (int nj = 0; nj < 2; ++nj) {
            float b0v = sb1[nbase + nj * 8 + 2 * tig];
            float b1v = sb1[nbase + nj * 8 + 2 * tig + 1];
            acc[mi][nj][0] = b0v; acc[mi][nj][1] = b1v;
            acc[mi][nj][2] = b0v; acc[mi][nj][3] = b1v;
        }
#pragma unroll
    for (int ki = 0; ki < 16; ++ki) {
        const int kb = ki * 8 + tig;
        float a[2][4], b[2][2];
#pragma unroll
        for (int mi = 0; mi < 2; ++mi) {
            const float* r0 = sX + (mbase + mi * 16 + gId) * 132;
            a[mi][0] = r0[kb];
            a[mi][1] = r0[8 * 132 + kb];
            a[mi][2] = r0[kb + 4];
            a[mi][3] = r0[8 * 132 + kb + 4];
        }
#pragma unroll
        for (int nj = 0; nj < 2; ++nj) {
            const float* bn = sW1t + (nbase + nj * 8 + gId) * 132;
            b[nj][0] = bn[kb];
            b[nj][1] = bn[kb + 4];
        }
#pragma unroll
        for (int mi = 0; mi < 2; ++mi)
#pragma unroll
            for (int nj = 0; nj < 2; ++nj)
                MMA_TF32(acc[mi][nj], a[mi], b[nj]);
    }
    // silu -> sU (tf32 rounded)
#pragma unroll
    for (int mi = 0; mi < 2; ++mi)
#pragma unroll
        for (int half = 0; half < 2; ++half) {
            int row = mbase + mi * 16 + gId + half * 8;
#pragma unroll
            for (int nj = 0; nj < 2; ++nj) {
                int col = nbase + nj * 8 + 2 * tig;
                float2 v = make_float2(
                    tf32r(silu_f(acc[mi][nj][half * 2])),
                    tf32r(silu_f(acc[mi][nj][half * 2 + 1])));
                *(float2*)(sU + row * 68 + col) = v;
            }
        }
    __syncthreads();

    // ---- layer 2 (K = 64) ----
    float acc2[2][2][4];
#pragma unroll
    for (int mi = 0; mi < 2; ++mi)
#pragma unroll
        for (int nj = 0; nj < 2; ++nj) {
            float b0v = sb2[nbase + nj * 8 + 2 * tig];
            float b1v = sb2[nbase + nj * 8 + 2 * tig + 1];
            acc2[mi][nj][0] = b0v; acc2[mi][nj][1] = b1v;
            acc2[mi][nj][2] = b0v; acc2[mi][nj][3] = b1v;
        }
#pragma unroll
    for (int ki = 0; ki < 8; ++ki) {
        const int kb = ki * 8 + tig;
        float a[2][4], b[2][2];
#pragma unroll
        for (int mi = 0; mi < 2; ++mi) {
            const float* r0 = sU + (mbase + mi * 16 + gId) * 68;
            a[mi][0] = r0[kb];
            a[mi][1] = r0[8 * 68 + kb];
            a[mi][2] = r0[kb + 4];
            a[mi][3] = r0[8 * 68 + kb + 4];
        }
#pragma unroll
        for (int nj = 0; nj < 2; ++nj) {
            const float* bn = sW2t + (nbase + nj * 8 + gId) * 68;
            b[nj][0] = bn[kb];
            b[nj][1] = bn[kb + 4];
        }
#pragma unroll
        for (int mi = 0; mi < 2; ++mi)
#pragma unroll
            for (int nj = 0; nj < 2; ++nj)
                MMA_TF32(acc2[mi][nj], a[mi], b[nj]);
    }

    // residual (full-precision h from g_hnew) + store
#pragma unroll
    for (int mi = 0; mi < 2; ++mi)
#pragma unroll
        for (int half = 0; half < 2; ++half) {
            int row = mbase + mi * 16 + gId + half * 8;
            int node = nb + row;
#pragma unroll
            for (int nj = 0; nj < 2; ++nj) {
                int col = nbase + nj * 8 + 2 * tig;
                float2 hv = *(const float2*)(g_hnew + (size_t)node * 64 + col);
                float2 v = make_float2(acc2[mi][nj][half * 2] + hv.x,
                                       acc2[mi][nj][half * 2 + 1] + hv.y);
                *(float2*)(out + (size_t)node * 64 + col) = v;
            }
        }
}

// ---------------------------------------------------------------------------
extern "C" void kernel_launch(void* const* d_in, const int* in_sizes, int n_in,
                              void* d_out, int out_size) {
    const float* h   = (const float*)d_in[0];
    const float* x   = (const float*)d_in[1];
    const float* vel = (const float*)d_in[2];
    const int*   ei  = (const int*)d_in[3];
    const float* whr = (const float*)d_in[4];
    const float* whi = (const float*)d_in[5];
    const float* wvr = (const float*)d_in[6];
    const float* wvi = (const float*)d_in[7];
    const float* We1 = (const float*)d_in[8];
    const float* be1 = (const float*)d_in[9];
    const float* We2 = (const float*)d_in[10];
    const float* be2 = (const float*)d_in[11];
    const float* Wg  = (const float*)d_in[12];
    const float* bg  = (const float*)d_in[13];
    const float* Wn1 = (const float*)d_in[14];
    const float* bn1 = (const float*)d_in[15];
    const float* Wn2 = (const float*)d_in[16];
    const float* bn2 = (const float*)d_in[17];
    float* out = (float*)d_out;

    (void)in_sizes; (void)n_in; (void)out_size;

    const int smem_h    = 24576 * 4;  // 98304
    const int smem_ab   = 13184 * 4;  // 52736
    const int smem_edge = 13632 * 4;  // 54528
    const int smem_node = 25728 * 4;  // 102912
    cudaFuncSetAttribute(k_time_h, cudaFuncAttributeMaxDynamicSharedMemorySize, smem_h);
    cudaFuncSetAttribute(k_ab,     cudaFuncAttributeMaxDynamicSharedMemorySize, smem_ab);
    cudaFuncSetAttribute(k_edge,   cudaFuncAttributeMaxDynamicSharedMemorySize, smem_edge);
    cudaFuncSetAttribute(k_node,   cudaFuncAttributeMaxDynamicSharedMemorySize, smem_node);

    // k_edge stays 4th so ncu captures it.
    k_d2<<<(E_ + 255) / 256, 256>>>(x, ei);
    k_time_h<<<1250, 256, smem_h>>>(h, whr, whi);
    k_ab<<<1250, 256, smem_ab>>>(We1, be1);
    k_edge<<<10000, 256, smem_edge>>>(ei, We1, We2, be2, Wg, bg);
    k_time_v<<<(BN_ * 3 + 255) / 256, 256>>>(vel, wvr, wvi, out + HTOT_);
    k_node<<<1250, 256, smem_node>>>(Wn1, bn1, Wn2, bn2, out);
}